// round 3
// baseline (speedup 1.0000x reference)
#include <cuda_runtime.h>
#include <math.h>

// Problem constants
#define BB   8
#define SS   1024
#define DD   1024
#define HH   16
#define HDIM 64
#define MR   (BB*SS)      // 8192 rows

// ---------------------------------------------------------------------------
// Scratch (device globals: allocation-free per harness rules)
// [B,H,S,HD] for q/k/v ; [B,S,D] for attention output and pre-LN x
// ---------------------------------------------------------------------------
__device__ float g_q[BB*HH*SS*HDIM];
__device__ float g_k[BB*HH*SS*HDIM];
__device__ float g_v[BB*HH*SS*HDIM];
__device__ float g_att[BB*SS*DD];
__device__ float g_x[BB*SS*DD];

// ---------------------------------------------------------------------------
// Kernel 1: fused QKV projection.
// C[m,n] = sum_k y[m,k] * W[n,k] + bias[n]   (torch Linear: y @ W^T + b)
// 128x128 tile, BK=8, 256 threads, 8x8 micro-tile per thread.
// grid.x = 24 (3 weights x 8 n-blocks), grid.y = 64 (m-blocks)
// Output written directly in [B,H,S,HD] layout.
// ---------------------------------------------------------------------------
__global__ __launch_bounds__(256) void qkv_gemm(
    const float* __restrict__ y,
    const float* __restrict__ Wq, const float* __restrict__ bq,
    const float* __restrict__ Wk, const float* __restrict__ bk,
    const float* __restrict__ Wv, const float* __restrict__ bv)
{
    __shared__ __align__(16) float As[8*128];
    __shared__ __align__(16) float Bs[8*128];

    int bn = blockIdx.x;
    int m0 = blockIdx.y * 128;
    int which = bn >> 3;
    const float* W;
    const float* bias;
    float* out;
    if (which == 0)      { W = Wq; bias = bq; out = g_q; }
    else if (which == 1) { W = Wk; bias = bk; out = g_k; }
    else                 { W = Wv; bias = bv; out = g_v; }
    int n0 = (bn & 7) * 128;

    int tid = threadIdx.x;
    int tx = tid & 15, ty = tid >> 4;
    int lr = tid >> 1;              // 0..127
    int kp = (tid & 1) * 4;         // 0 or 4

    float acc[8][8];
    #pragma unroll
    for (int i = 0; i < 8; i++)
        #pragma unroll
        for (int j = 0; j < 8; j++) acc[i][j] = 0.f;

    const float* aptr = y + (size_t)(m0 + lr) * DD + kp;
    const float* bptr = W + (size_t)(n0 + lr) * DD + kp;

    for (int k0 = 0; k0 < DD; k0 += 8) {
        float4 a4 = *(const float4*)(aptr + k0);
        float4 b4 = *(const float4*)(bptr + k0);
        __syncthreads();
        As[(kp + 0)*128 + lr] = a4.x; As[(kp + 1)*128 + lr] = a4.y;
        As[(kp + 2)*128 + lr] = a4.z; As[(kp + 3)*128 + lr] = a4.w;
        Bs[(kp + 0)*128 + lr] = b4.x; Bs[(kp + 1)*128 + lr] = b4.y;
        Bs[(kp + 2)*128 + lr] = b4.z; Bs[(kp + 3)*128 + lr] = b4.w;
        __syncthreads();

        #pragma unroll
        for (int k = 0; k < 8; k++) {
            float4 a0 = *(const float4*)&As[k*128 + ty*8];
            float4 a1 = *(const float4*)&As[k*128 + ty*8 + 4];
            float4 b0 = *(const float4*)&Bs[k*128 + tx*8];
            float4 b1 = *(const float4*)&Bs[k*128 + tx*8 + 4];
            float a[8] = {a0.x,a0.y,a0.z,a0.w,a1.x,a1.y,a1.z,a1.w};
            float b[8] = {b0.x,b0.y,b0.z,b0.w,b1.x,b1.y,b1.z,b1.w};
            #pragma unroll
            for (int i = 0; i < 8; i++)
                #pragma unroll
                for (int j = 0; j < 8; j++)
                    acc[i][j] = fmaf(a[i], b[j], acc[i][j]);
        }
    }

    // Epilogue: scatter into [B,H,S,HD]
    #pragma unroll
    for (int i = 0; i < 8; i++) {
        int m = m0 + ty*8 + i;
        int b = m >> 10, s = m & 1023;
        #pragma unroll
        for (int j = 0; j < 8; j++) {
            int n = n0 + tx*8 + j;
            int h = n >> 6, hd = n & 63;
            out[(((size_t)(b*HH + h))*SS + s)*HDIM + hd] = acc[i][j] + bias[n];
        }
    }
}

// ---------------------------------------------------------------------------
// Kernel 2: flash-attention style fused attention per (b, h, q-tile of 64).
// Online softmax; scores never touch HBM. Mask (key positions, int32 0/1)
// -> exact -1e9, matching the reference's jnp.where.
// Dynamic smem: Qs[64][64], Ks[64][65], Vs[64][65]  (49664 B)
// ---------------------------------------------------------------------------
#define ATTN_SMEM ((64*64 + 64*65 + 64*65) * 4)

__global__ __launch_bounds__(256) void attn_kernel(const int* __restrict__ mask)
{
    extern __shared__ __align__(16) float sm[];
    float* Qs = sm;                  // ld 64
    float* Ks = sm + 64*64;          // ld 65 (also reused as P buffer)
    float* Vs = Ks + 64*65;          // ld 65

    int qt = blockIdx.x, h = blockIdx.y, b = blockIdx.z;
    const float* Q  = g_q + ((size_t)(b*HH + h)*SS + qt*64) * HDIM;
    const float* K0 = g_k + ((size_t)(b*HH + h)*SS) * HDIM;
    const float* V0 = g_v + ((size_t)(b*HH + h)*SS) * HDIM;

    int tid = threadIdx.x, tx = tid & 15, ty = tid >> 4;

    // Load Q tile (64x64 floats)
    #pragma unroll
    for (int it = 0; it < 4; it++) {
        int idx = tid + it*256;            // float4 index 0..1023
        int r = idx >> 4, c = (idx & 15) * 4;
        float4 q4 = *(const float4*)(Q + r*64 + c);
        Qs[r*64 + c + 0] = q4.x; Qs[r*64 + c + 1] = q4.y;
        Qs[r*64 + c + 2] = q4.z; Qs[r*64 + c + 3] = q4.w;
    }

    float acc[4][4];
    float mrow[4], lrow[4];
    #pragma unroll
    for (int i = 0; i < 4; i++) {
        mrow[i] = -3.0e38f; lrow[i] = 0.f;
        #pragma unroll
        for (int j = 0; j < 4; j++) acc[i][j] = 0.f;
    }

    for (int t = 0; t < 16; t++) {
        const float* K = K0 + (size_t)t*64*HDIM;
        const float* V = V0 + (size_t)t*64*HDIM;
        __syncthreads();   // prior PV readers done before overwrite
        #pragma unroll
        for (int it = 0; it < 4; it++) {
            int idx = tid + it*256;
            int r = idx >> 4, c = (idx & 15) * 4;
            float4 k4 = *(const float4*)(K + r*64 + c);
            Ks[r*65 + c + 0] = k4.x; Ks[r*65 + c + 1] = k4.y;
            Ks[r*65 + c + 2] = k4.z; Ks[r*65 + c + 3] = k4.w;
            float4 v4 = *(const float4*)(V + r*64 + c);
            Vs[r*65 + c + 0] = v4.x; Vs[r*65 + c + 1] = v4.y;
            Vs[r*65 + c + 2] = v4.z; Vs[r*65 + c + 3] = v4.w;
        }
        __syncthreads();

        // S = Q @ K^T for this thread's 4x4 patch
        float s[4][4];
        #pragma unroll
        for (int i = 0; i < 4; i++)
            #pragma unroll
            for (int j = 0; j < 4; j++) s[i][j] = 0.f;
        #pragma unroll 8
        for (int d = 0; d < 64; d++) {
            float qv[4], kv[4];
            #pragma unroll
            for (int i = 0; i < 4; i++) qv[i] = Qs[(ty*4 + i)*64 + d];
            #pragma unroll
            for (int j = 0; j < 4; j++) kv[j] = Ks[(tx*4 + j)*65 + d];
            #pragma unroll
            for (int i = 0; i < 4; i++)
                #pragma unroll
                for (int j = 0; j < 4; j++)
                    s[i][j] = fmaf(qv[i], kv[j], s[i][j]);
        }

        // scale 1/sqrt(64), then key-mask -> exact -1e9 (matches reference).
        // Mask is int32 (jax bool materialized as int32 by the harness).
        int4 m4 = *(const int4*)(mask + b*SS + t*64 + tx*4);
        int mb[4] = {m4.x, m4.y, m4.z, m4.w};
        #pragma unroll
        for (int j = 0; j < 4; j++) {
            bool km = (mb[j] != 0);
            #pragma unroll
            for (int i = 0; i < 4; i++)
                s[i][j] = km ? -1e9f : s[i][j] * 0.125f;
        }

        // online softmax update (row reductions across the 16 tx lanes)
        #pragma unroll
        for (int i = 0; i < 4; i++) {
            float tm = fmaxf(fmaxf(s[i][0], s[i][1]), fmaxf(s[i][2], s[i][3]));
            #pragma unroll
            for (int m = 1; m < 16; m <<= 1)
                tm = fmaxf(tm, __shfl_xor_sync(0xffffffffu, tm, m));
            float mn = fmaxf(mrow[i], tm);
            float alpha = __expf(mrow[i] - mn);
            float ps = 0.f;
            #pragma unroll
            for (int j = 0; j < 4; j++) {
                s[i][j] = __expf(s[i][j] - mn);
                ps += s[i][j];
            }
            #pragma unroll
            for (int m = 1; m < 16; m <<= 1)
                ps += __shfl_xor_sync(0xffffffffu, ps, m);
            lrow[i] = lrow[i] * alpha + ps;
            mrow[i] = mn;
            #pragma unroll
            for (int j = 0; j < 4; j++) acc[i][j] *= alpha;
        }

        __syncthreads();   // everyone done reading Ks before P overwrite
        #pragma unroll
        for (int i = 0; i < 4; i++)
            #pragma unroll
            for (int j = 0; j < 4; j++)
                Ks[(ty*4 + i)*65 + tx*4 + j] = s[i][j];
        __syncthreads();

        // acc += P @ V
        #pragma unroll 8
        for (int j = 0; j < 64; j++) {
            float p[4], vv[4];
            #pragma unroll
            for (int i = 0; i < 4; i++) p[i] = Ks[(ty*4 + i)*65 + j];
            #pragma unroll
            for (int c = 0; c < 4; c++) vv[c] = Vs[j*65 + tx*4 + c];
            #pragma unroll
            for (int i = 0; i < 4; i++)
                #pragma unroll
                for (int c = 0; c < 4; c++)
                    acc[i][c] = fmaf(p[i], vv[c], acc[i][c]);
        }
    }

    // normalize and write to [B,S,D]
    #pragma unroll
    for (int i = 0; i < 4; i++) {
        float inv = 1.f / lrow[i];
        int srow = qt*64 + ty*4 + i;
        #pragma unroll
        for (int c = 0; c < 4; c++)
            g_att[((size_t)(b*SS + srow))*DD + h*HDIM + tx*4 + c] = acc[i][c] * inv;
    }
}

// ---------------------------------------------------------------------------
// Kernel 3: output projection + residual.  g_x = att @ Wm^T + bm + y
// Same GEMM skeleton. grid (8, 64).
// ---------------------------------------------------------------------------
__global__ __launch_bounds__(256) void proj_gemm(
    const float* __restrict__ Wm, const float* __restrict__ bm,
    const float* __restrict__ y)
{
    __shared__ __align__(16) float As[8*128];
    __shared__ __align__(16) float Bs[8*128];

    int n0 = blockIdx.x * 128;
    int m0 = blockIdx.y * 128;
    int tid = threadIdx.x;
    int tx = tid & 15, ty = tid >> 4;
    int lr = tid >> 1;
    int kp = (tid & 1) * 4;

    float acc[8][8];
    #pragma unroll
    for (int i = 0; i < 8; i++)
        #pragma unroll
        for (int j = 0; j < 8; j++) acc[i][j] = 0.f;

    const float* aptr = g_att + (size_t)(m0 + lr) * DD + kp;
    const float* bptr = Wm + (size_t)(n0 + lr) * DD + kp;

    for (int k0 = 0; k0 < DD; k0 += 8) {
        float4 a4 = *(const float4*)(aptr + k0);
        float4 b4 = *(const float4*)(bptr + k0);
        __syncthreads();
        As[(kp + 0)*128 + lr] = a4.x; As[(kp + 1)*128 + lr] = a4.y;
        As[(kp + 2)*128 + lr] = a4.z; As[(kp + 3)*128 + lr] = a4.w;
        Bs[(kp + 0)*128 + lr] = b4.x; Bs[(kp + 1)*128 + lr] = b4.y;
        Bs[(kp + 2)*128 + lr] = b4.z; Bs[(kp + 3)*128 + lr] = b4.w;
        __syncthreads();

        #pragma unroll
        for (int k = 0; k < 8; k++) {
            float4 a0 = *(const float4*)&As[k*128 + ty*8];
            float4 a1 = *(const float4*)&As[k*128 + ty*8 + 4];
            float4 b0 = *(const float4*)&Bs[k*128 + tx*8];
            float4 b1 = *(const float4*)&Bs[k*128 + tx*8 + 4];
            float a[8] = {a0.x,a0.y,a0.z,a0.w,a1.x,a1.y,a1.z,a1.w};
            float b[8] = {b0.x,b0.y,b0.z,b0.w,b1.x,b1.y,b1.z,b1.w};
            #pragma unroll
            for (int i = 0; i < 8; i++)
                #pragma unroll
                for (int j = 0; j < 8; j++)
                    acc[i][j] = fmaf(a[i], b[j], acc[i][j]);
        }
    }

    #pragma unroll
    for (int i = 0; i < 8; i++) {
        int m = m0 + ty*8 + i;
        #pragma unroll
        for (int j = 0; j < 8; j++) {
            int n = n0 + tx*8 + j;
            g_x[(size_t)m*DD + n] = acc[i][j] + bm[n] + y[(size_t)m*DD + n];
        }
    }
}

// ---------------------------------------------------------------------------
// Kernel 4: LayerNorm (torch semantics: unbiased std, eps added to std).
// One block per row; row held in registers (4 floats/thread).
// ---------------------------------------------------------------------------
__global__ __launch_bounds__(256) void ln_kernel(
    const float* __restrict__ a2, const float* __restrict__ b2,
    float* __restrict__ out)
{
    __shared__ float ws[8];
    int row = blockIdx.x;
    int tid = threadIdx.x;
    int lane = tid & 31, wid = tid >> 5;

    const float* x = g_x + (size_t)row * DD;
    float4 v = *(const float4*)(x + tid*4);

    float s = v.x + v.y + v.z + v.w;
    #pragma unroll
    for (int m = 16; m; m >>= 1) s += __shfl_xor_sync(0xffffffffu, s, m);
    if (lane == 0) ws[wid] = s;
    __syncthreads();
    float tot = 0.f;
    #pragma unroll
    for (int i = 0; i < 8; i++) tot += ws[i];
    float mean = tot * (1.f / 1024.f);
    __syncthreads();

    float d0 = v.x - mean, d1 = v.y - mean, d2 = v.z - mean, d3 = v.w - mean;
    float ss = d0*d0 + d1*d1 + d2*d2 + d3*d3;
    #pragma unroll
    for (int m = 16; m; m >>= 1) ss += __shfl_xor_sync(0xffffffffu, ss, m);
    if (lane == 0) ws[wid] = ss;
    __syncthreads();
    float sst = 0.f;
    #pragma unroll
    for (int i = 0; i < 8; i++) sst += ws[i];

    float stdv = sqrtf(sst * (1.f / 1023.f));   // ddof = 1
    float inv = 1.f / (stdv + 1e-6f);           // eps on std

    float4 a = *(const float4*)(a2 + tid*4);
    float4 bb = *(const float4*)(b2 + tid*4);
    float4 o;
    o.x = a.x * d0 * inv + bb.x;
    o.y = a.y * d1 * inv + bb.y;
    o.z = a.z * d2 * inv + bb.z;
    o.w = a.w * d3 * inv + bb.w;
    *(float4*)(out + (size_t)row * DD + tid*4) = o;
}

// ---------------------------------------------------------------------------
// Launch
// ---------------------------------------------------------------------------
extern "C" void kernel_launch(void* const* d_in, const int* in_sizes, int n_in,
                              void* d_out, int out_size)
{
    (void)in_sizes; (void)n_in; (void)out_size;
    const float* y  = (const float*)d_in[0];
    const int* ym   = (const int*)d_in[1];    // jax bool materialized as int32
    const float* Wq = (const float*)d_in[2];
    const float* bq = (const float*)d_in[3];
    const float* Wk = (const float*)d_in[4];
    const float* bk = (const float*)d_in[5];
    const float* Wv = (const float*)d_in[6];
    const float* bv = (const float*)d_in[7];
    const float* Wm = (const float*)d_in[8];
    const float* bm = (const float*)d_in[9];
    const float* a2 = (const float*)d_in[10];
    const float* b2 = (const float*)d_in[11];
    float* out = (float*)d_out;

    // Opt-in to >48KB dynamic smem for the attention kernel (not an allocation;
    // idempotent, graph-capture safe — no stream interaction).
    cudaFuncSetAttribute(attn_kernel,
                         cudaFuncAttributeMaxDynamicSharedMemorySize, ATTN_SMEM);

    qkv_gemm<<<dim3(24, 64), 256>>>(y, Wq, bq, Wk, bk, Wv, bv);
    attn_kernel<<<dim3(16, 16, 8), 256, ATTN_SMEM>>>(ym);
    proj_gemm<<<dim3(8, 64), 256>>>(Wm, bm, y);
    ln_kernel<<<MR, 256>>>(a2, b2, out);
}

// round 5
// speedup vs baseline: 1.8235x; 1.8235x over previous
#include <cuda_runtime.h>
#include <math.h>

// Problem constants
#define BB   8
#define SS   1024
#define DD   1024
#define HH   16
#define HDIM 64
#define MR   (BB*SS)      // 8192 rows

// ---------------------------------------------------------------------------
// Scratch (device globals: allocation-free per harness rules)
// ---------------------------------------------------------------------------
__device__ float g_q[BB*HH*SS*HDIM];
__device__ float g_k[BB*HH*SS*HDIM];
__device__ float g_v[BB*HH*SS*HDIM];
__device__ float g_att[BB*SS*DD];
__device__ float g_x[BB*SS*DD];

// ---------------------------------------------------------------------------
// tf32 mma.sync helpers
// ---------------------------------------------------------------------------
__device__ __forceinline__ unsigned f2tf(float f) {
    unsigned u;
    asm("cvt.rna.tf32.f32 %0, %1;" : "=r"(u) : "f"(f));
    return u;
}

__device__ __forceinline__ void mma_tf32(float* d, const unsigned* a, const unsigned* b) {
    asm volatile(
        "mma.sync.aligned.m16n8k8.row.col.f32.tf32.tf32.f32 "
        "{%0,%1,%2,%3}, {%4,%5,%6,%7}, {%8,%9}, {%0,%1,%2,%3};"
        : "+f"(d[0]), "+f"(d[1]), "+f"(d[2]), "+f"(d[3])
        : "r"(a[0]), "r"(a[1]), "r"(a[2]), "r"(a[3]),
          "r"(b[0]), "r"(b[1]));
}

// Shared-tile pitch: 36 floats per 32-wide k-row makes fragment loads
// conflict-free (bank = (4*row + col) % 32, bijective across a warp).
#define SPITCH 36

// ---------------------------------------------------------------------------
// tf32 GEMM mainloop (shared by qkv and proj kernels).
// Computes acc[mf*4+nf][0..3] for C = A @ B^T on a 128x128 tile, K=1024.
// A: [*,1024] rows m0.., B: [*,1024] rows n0..  (both row-major, K contiguous)
// ---------------------------------------------------------------------------
__device__ __forceinline__ void gemm_tf32_main(
    const float* __restrict__ Ag, const float* __restrict__ Bg,
    int m0, int n0, int tid,
    unsigned* As, unsigned* Bs, float acc[16][4])
{
    int lane = tid & 31, gid = lane >> 2, tig = lane & 3;
    int warp = tid >> 5, wm = warp & 1, wn = warp >> 1;

    int lrow = tid >> 3;          // 0..31
    int lcol = (tid & 7) * 4;     // 0,4,...,28

    float4 pa[4], pb[4];
    #pragma unroll
    for (int it = 0; it < 4; it++) {
        pa[it] = *(const float4*)&Ag[(size_t)(m0 + lrow + it*32)*DD + lcol];
        pb[it] = *(const float4*)&Bg[(size_t)(n0 + lrow + it*32)*DD + lcol];
    }

    for (int k0 = 0; k0 < DD; k0 += 32) {
        __syncthreads();
        #pragma unroll
        for (int it = 0; it < 4; it++) {
            int r = lrow + it*32;
            As[r*SPITCH + lcol + 0] = f2tf(pa[it].x);
            As[r*SPITCH + lcol + 1] = f2tf(pa[it].y);
            As[r*SPITCH + lcol + 2] = f2tf(pa[it].z);
            As[r*SPITCH + lcol + 3] = f2tf(pa[it].w);
            Bs[r*SPITCH + lcol + 0] = f2tf(pb[it].x);
            Bs[r*SPITCH + lcol + 1] = f2tf(pb[it].y);
            Bs[r*SPITCH + lcol + 2] = f2tf(pb[it].z);
            Bs[r*SPITCH + lcol + 3] = f2tf(pb[it].w);
        }
        __syncthreads();

        if (k0 + 32 < DD) {
            #pragma unroll
            for (int it = 0; it < 4; it++) {
                pa[it] = *(const float4*)&Ag[(size_t)(m0 + lrow + it*32)*DD + k0 + 32 + lcol];
                pb[it] = *(const float4*)&Bg[(size_t)(n0 + lrow + it*32)*DD + k0 + 32 + lcol];
            }
        }

        #pragma unroll
        for (int k8 = 0; k8 < 4; k8++) {
            int kc = k8*8 + tig;
            unsigned a[4][4], b[4][2];
            #pragma unroll
            for (int mf = 0; mf < 4; mf++) {
                int r = wm*64 + mf*16 + gid;
                a[mf][0] = As[r*SPITCH + kc];
                a[mf][1] = As[(r+8)*SPITCH + kc];
                a[mf][2] = As[r*SPITCH + kc + 4];
                a[mf][3] = As[(r+8)*SPITCH + kc + 4];
            }
            #pragma unroll
            for (int nf = 0; nf < 4; nf++) {
                int n = wn*32 + nf*8 + gid;
                b[nf][0] = Bs[n*SPITCH + kc];
                b[nf][1] = Bs[n*SPITCH + kc + 4];
            }
            #pragma unroll
            for (int mf = 0; mf < 4; mf++)
                #pragma unroll
                for (int nf = 0; nf < 4; nf++)
                    mma_tf32(acc[mf*4 + nf], a[mf], b[nf]);
        }
    }
}

// ---------------------------------------------------------------------------
// Kernel 1: fused QKV projection (tf32 tensor cores).
// grid.x = 24 (3 weights x 8 n-blocks), grid.y = 64 (m-blocks). 256 thr.
// Output scattered into [B,H,S,HD].
// ---------------------------------------------------------------------------
__global__ __launch_bounds__(256) void qkv_gemm(
    const float* __restrict__ y,
    const float* __restrict__ Wq, const float* __restrict__ bq,
    const float* __restrict__ Wk, const float* __restrict__ bk,
    const float* __restrict__ Wv, const float* __restrict__ bv)
{
    __shared__ __align__(16) unsigned As[128*SPITCH];
    __shared__ __align__(16) unsigned Bs[128*SPITCH];

    int bn = blockIdx.x;
    int m0 = blockIdx.y * 128;
    int which = bn >> 3;
    const float* W; const float* bias; float* out;
    if (which == 0)      { W = Wq; bias = bq; out = g_q; }
    else if (which == 1) { W = Wk; bias = bk; out = g_k; }
    else                 { W = Wv; bias = bv; out = g_v; }
    int n0 = (bn & 7) * 128;

    int tid = threadIdx.x;
    float acc[16][4];
    #pragma unroll
    for (int i = 0; i < 16; i++)
        #pragma unroll
        for (int j = 0; j < 4; j++) acc[i][j] = 0.f;

    gemm_tf32_main(y, W, m0, n0, tid, As, Bs, acc);

    int lane = tid & 31, gid = lane >> 2, tig = lane & 3;
    int warp = tid >> 5, wm = warp & 1, wn = warp >> 1;

    #pragma unroll
    for (int mf = 0; mf < 4; mf++) {
        #pragma unroll
        for (int nf = 0; nf < 4; nf++) {
            float* c = acc[mf*4 + nf];
            int n = n0 + wn*32 + nf*8 + 2*tig;
            int h = n >> 6, hd = n & 63;
            float bx = bias[n], by = bias[n+1];
            int m = m0 + wm*64 + mf*16 + gid;
            int bi = m >> 10, s = m & 1023;
            float2 v0 = make_float2(c[0] + bx, c[1] + by);
            *(float2*)&out[(((size_t)(bi*HH + h))*SS + s)*HDIM + hd] = v0;
            m += 8; bi = m >> 10; s = m & 1023;
            float2 v1 = make_float2(c[2] + bx, c[3] + by);
            *(float2*)&out[(((size_t)(bi*HH + h))*SS + s)*HDIM + hd] = v1;
        }
    }
}

// ---------------------------------------------------------------------------
// Kernel 3: output projection + residual (tf32).  g_x = att @ Wm^T + bm + y
// grid (8, 64), 256 threads.
// ---------------------------------------------------------------------------
__global__ __launch_bounds__(256) void proj_gemm(
    const float* __restrict__ Wm, const float* __restrict__ bm,
    const float* __restrict__ y)
{
    __shared__ __align__(16) unsigned As[128*SPITCH];
    __shared__ __align__(16) unsigned Bs[128*SPITCH];

    int n0 = blockIdx.x * 128;
    int m0 = blockIdx.y * 128;
    int tid = threadIdx.x;

    float acc[16][4];
    #pragma unroll
    for (int i = 0; i < 16; i++)
        #pragma unroll
        for (int j = 0; j < 4; j++) acc[i][j] = 0.f;

    gemm_tf32_main(g_att, Wm, m0, n0, tid, As, Bs, acc);

    int lane = tid & 31, gid = lane >> 2, tig = lane & 3;
    int warp = tid >> 5, wm = warp & 1, wn = warp >> 1;

    #pragma unroll
    for (int mf = 0; mf < 4; mf++) {
        #pragma unroll
        for (int nf = 0; nf < 4; nf++) {
            float* c = acc[mf*4 + nf];
            int n = n0 + wn*32 + nf*8 + 2*tig;
            float bx = bm[n], by = bm[n+1];
            int m = m0 + wm*64 + mf*16 + gid;
            size_t o = (size_t)m*DD + n;
            float2 r0 = *(const float2*)&y[o];
            *(float2*)&g_x[o] = make_float2(c[0] + bx + r0.x, c[1] + by + r0.y);
            o += (size_t)8*DD;
            float2 r1 = *(const float2*)&y[o];
            *(float2*)&g_x[o] = make_float2(c[2] + bx + r1.x, c[3] + by + r1.y);
        }
    }
}

// ---------------------------------------------------------------------------
// Kernel 2: flash-attention style fused attention (fp32 SIMT, unchanged).
// ---------------------------------------------------------------------------
#define ATTN_SMEM ((64*64 + 64*65 + 64*65) * 4)

__global__ __launch_bounds__(256) void attn_kernel(const int* __restrict__ mask)
{
    extern __shared__ __align__(16) float sm[];
    float* Qs = sm;                  // ld 64
    float* Ks = sm + 64*64;          // ld 65 (also reused as P buffer)
    float* Vs = Ks + 64*65;          // ld 65

    int qt = blockIdx.x, h = blockIdx.y, b = blockIdx.z;
    const float* Q  = g_q + ((size_t)(b*HH + h)*SS + qt*64) * HDIM;
    const float* K0 = g_k + ((size_t)(b*HH + h)*SS) * HDIM;
    const float* V0 = g_v + ((size_t)(b*HH + h)*SS) * HDIM;

    int tid = threadIdx.x, tx = tid & 15, ty = tid >> 4;

    #pragma unroll
    for (int it = 0; it < 4; it++) {
        int idx = tid + it*256;
        int r = idx >> 4, c = (idx & 15) * 4;
        float4 q4 = *(const float4*)(Q + r*64 + c);
        Qs[r*64 + c + 0] = q4.x; Qs[r*64 + c + 1] = q4.y;
        Qs[r*64 + c + 2] = q4.z; Qs[r*64 + c + 3] = q4.w;
    }

    float acc[4][4];
    float mrow[4], lrow[4];
    #pragma unroll
    for (int i = 0; i < 4; i++) {
        mrow[i] = -3.0e38f; lrow[i] = 0.f;
        #pragma unroll
        for (int j = 0; j < 4; j++) acc[i][j] = 0.f;
    }

    for (int t = 0; t < 16; t++) {
        const float* K = K0 + (size_t)t*64*HDIM;
        const float* V = V0 + (size_t)t*64*HDIM;
        __syncthreads();
        #pragma unroll
        for (int it = 0; it < 4; it++) {
            int idx = tid + it*256;
            int r = idx >> 4, c = (idx & 15) * 4;
            float4 k4 = *(const float4*)(K + r*64 + c);
            Ks[r*65 + c + 0] = k4.x; Ks[r*65 + c + 1] = k4.y;
            Ks[r*65 + c + 2] = k4.z; Ks[r*65 + c + 3] = k4.w;
            float4 v4 = *(const float4*)(V + r*64 + c);
            Vs[r*65 + c + 0] = v4.x; Vs[r*65 + c + 1] = v4.y;
            Vs[r*65 + c + 2] = v4.z; Vs[r*65 + c + 3] = v4.w;
        }
        __syncthreads();

        float s[4][4];
        #pragma unroll
        for (int i = 0; i < 4; i++)
            #pragma unroll
            for (int j = 0; j < 4; j++) s[i][j] = 0.f;
        #pragma unroll 8
        for (int d = 0; d < 64; d++) {
            float qv[4], kv[4];
            #pragma unroll
            for (int i = 0; i < 4; i++) qv[i] = Qs[(ty*4 + i)*64 + d];
            #pragma unroll
            for (int j = 0; j < 4; j++) kv[j] = Ks[(tx*4 + j)*65 + d];
            #pragma unroll
            for (int i = 0; i < 4; i++)
                #pragma unroll
                for (int j = 0; j < 4; j++)
                    s[i][j] = fmaf(qv[i], kv[j], s[i][j]);
        }

        int4 m4 = *(const int4*)(mask + b*SS + t*64 + tx*4);
        int mb[4] = {m4.x, m4.y, m4.z, m4.w};
        #pragma unroll
        for (int j = 0; j < 4; j++) {
            bool km = (mb[j] != 0);
            #pragma unroll
            for (int i = 0; i < 4; i++)
                s[i][j] = km ? -1e9f : s[i][j] * 0.125f;
        }

        #pragma unroll
        for (int i = 0; i < 4; i++) {
            float tm = fmaxf(fmaxf(s[i][0], s[i][1]), fmaxf(s[i][2], s[i][3]));
            #pragma unroll
            for (int m = 1; m < 16; m <<= 1)
                tm = fmaxf(tm, __shfl_xor_sync(0xffffffffu, tm, m));
            float mn = fmaxf(mrow[i], tm);
            float alpha = __expf(mrow[i] - mn);
            float ps = 0.f;
            #pragma unroll
            for (int j = 0; j < 4; j++) {
                s[i][j] = __expf(s[i][j] - mn);
                ps += s[i][j];
            }
            #pragma unroll
            for (int m = 1; m < 16; m <<= 1)
                ps += __shfl_xor_sync(0xffffffffu, ps, m);
            lrow[i] = lrow[i] * alpha + ps;
            mrow[i] = mn;
            #pragma unroll
            for (int j = 0; j < 4; j++) acc[i][j] *= alpha;
        }

        __syncthreads();
        #pragma unroll
        for (int i = 0; i < 4; i++)
            #pragma unroll
            for (int j = 0; j < 4; j++)
                Ks[(ty*4 + i)*65 + tx*4 + j] = s[i][j];
        __syncthreads();

        #pragma unroll 8
        for (int j = 0; j < 64; j++) {
            float p[4], vv[4];
            #pragma unroll
            for (int i = 0; i < 4; i++) p[i] = Ks[(ty*4 + i)*65 + j];
            #pragma unroll
            for (int c = 0; c < 4; c++) vv[c] = Vs[j*65 + tx*4 + c];
            #pragma unroll
            for (int i = 0; i < 4; i++)
                #pragma unroll
                for (int c = 0; c < 4; c++)
                    acc[i][c] = fmaf(p[i], vv[c], acc[i][c]);
        }
    }

    #pragma unroll
    for (int i = 0; i < 4; i++) {
        float inv = 1.f / lrow[i];
        int srow = qt*64 + ty*4 + i;
        #pragma unroll
        for (int c = 0; c < 4; c++)
            g_att[((size_t)(b*SS + srow))*DD + h*HDIM + tx*4 + c] = acc[i][c] * inv;
    }
}

// ---------------------------------------------------------------------------
// Kernel 4: LayerNorm (torch semantics: unbiased std, eps added to std).
// ---------------------------------------------------------------------------
__global__ __launch_bounds__(256) void ln_kernel(
    const float* __restrict__ a2, const float* __restrict__ b2,
    float* __restrict__ out)
{
    __shared__ float ws[8];
    int row = blockIdx.x;
    int tid = threadIdx.x;
    int lane = tid & 31, wid = tid >> 5;

    const float* x = g_x + (size_t)row * DD;
    float4 v = *(const float4*)(x + tid*4);

    float s = v.x + v.y + v.z + v.w;
    #pragma unroll
    for (int m = 16; m; m >>= 1) s += __shfl_xor_sync(0xffffffffu, s, m);
    if (lane == 0) ws[wid] = s;
    __syncthreads();
    float tot = 0.f;
    #pragma unroll
    for (int i = 0; i < 8; i++) tot += ws[i];
    float mean = tot * (1.f / 1024.f);
    __syncthreads();

    float d0 = v.x - mean, d1 = v.y - mean, d2 = v.z - mean, d3 = v.w - mean;
    float ss = d0*d0 + d1*d1 + d2*d2 + d3*d3;
    #pragma unroll
    for (int m = 16; m; m >>= 1) ss += __shfl_xor_sync(0xffffffffu, ss, m);
    if (lane == 0) ws[wid] = ss;
    __syncthreads();
    float sst = 0.f;
    #pragma unroll
    for (int i = 0; i < 8; i++) sst += ws[i];

    float stdv = sqrtf(sst * (1.f / 1023.f));   // ddof = 1
    float inv = 1.f / (stdv + 1e-6f);           // eps on std

    float4 a = *(const float4*)(a2 + tid*4);
    float4 bb = *(const float4*)(b2 + tid*4);
    float4 o;
    o.x = a.x * d0 * inv + bb.x;
    o.y = a.y * d1 * inv + bb.y;
    o.z = a.z * d2 * inv + bb.z;
    o.w = a.w * d3 * inv + bb.w;
    *(float4*)(out + (size_t)row * DD + tid*4) = o;
}

// ---------------------------------------------------------------------------
// Launch
// ---------------------------------------------------------------------------
extern "C" void kernel_launch(void* const* d_in, const int* in_sizes, int n_in,
                              void* d_out, int out_size)
{
    (void)in_sizes; (void)n_in; (void)out_size;
    const float* y  = (const float*)d_in[0];
    const int* ym   = (const int*)d_in[1];    // jax bool materialized as int32
    const float* Wq = (const float*)d_in[2];
    const float* bq = (const float*)d_in[3];
    const float* Wk = (const float*)d_in[4];
    const float* bk = (const float*)d_in[5];
    const float* Wv = (const float*)d_in[6];
    const float* bv = (const float*)d_in[7];
    const float* Wm = (const float*)d_in[8];
    const float* bm = (const float*)d_in[9];
    const float* a2 = (const float*)d_in[10];
    const float* b2 = (const float*)d_in[11];
    float* out = (float*)d_out;

    cudaFuncSetAttribute(attn_kernel,
                         cudaFuncAttributeMaxDynamicSharedMemorySize, ATTN_SMEM);

    qkv_gemm<<<dim3(24, 64), 256>>>(y, Wq, bq, Wk, bk, Wv, bv);
    attn_kernel<<<dim3(16, 16, 8), 256, ATTN_SMEM>>>(ym);
    proj_gemm<<<dim3(8, 64), 256>>>(Wm, bm, y);
    ln_kernel<<<MR, 256>>>(a2, b2, out);
}

// round 8
// speedup vs baseline: 3.4335x; 1.8829x over previous
#include <cuda_runtime.h>
#include <math.h>

// Problem constants
#define BB   8
#define SS   1024
#define DD   1024
#define HH   16
#define HDIM 64
#define MR   (BB*SS)      // 8192 rows

// ---------------------------------------------------------------------------
// Scratch (device globals: allocation-free per harness rules)
// ---------------------------------------------------------------------------
__device__ float g_q[BB*HH*SS*HDIM];
__device__ float g_k[BB*HH*SS*HDIM];
__device__ float g_v[BB*HH*SS*HDIM];
__device__ float g_att[BB*SS*DD];
__device__ float g_x[BB*SS*DD];

// ---------------------------------------------------------------------------
// tf32 mma.sync helpers
// ---------------------------------------------------------------------------
__device__ __forceinline__ unsigned f2tf(float f) {
    unsigned u;
    asm("cvt.rna.tf32.f32 %0, %1;" : "=r"(u) : "f"(f));
    return u;
}

__device__ __forceinline__ void mma_tf32(float* d, const unsigned* a, const unsigned* b) {
    asm volatile(
        "mma.sync.aligned.m16n8k8.row.col.f32.tf32.tf32.f32 "
        "{%0,%1,%2,%3}, {%4,%5,%6,%7}, {%8,%9}, {%0,%1,%2,%3};"
        : "+f"(d[0]), "+f"(d[1]), "+f"(d[2]), "+f"(d[3])
        : "r"(a[0]), "r"(a[1]), "r"(a[2]), "r"(a[3]),
          "r"(b[0]), "r"(b[1]));
}

// Shared-tile pitch for the projection GEMMs (conflict-free fragment loads).
#define SPITCH 36

// ---------------------------------------------------------------------------
// tf32 GEMM mainloop (shared by qkv and proj kernels).  C = A @ B^T,
// 128x128 tile, K=1024.  (Measured working in R5.)
// ---------------------------------------------------------------------------
__device__ __forceinline__ void gemm_tf32_main(
    const float* __restrict__ Ag, const float* __restrict__ Bg,
    int m0, int n0, int tid,
    unsigned* As, unsigned* Bs, float acc[16][4])
{
    int lane = tid & 31, gid = lane >> 2, tig = lane & 3;
    int warp = tid >> 5, wm = warp & 1, wn = warp >> 1;

    int lrow = tid >> 3;          // 0..31
    int lcol = (tid & 7) * 4;     // 0,4,...,28

    float4 pa[4], pb[4];
    #pragma unroll
    for (int it = 0; it < 4; it++) {
        pa[it] = *(const float4*)&Ag[(size_t)(m0 + lrow + it*32)*DD + lcol];
        pb[it] = *(const float4*)&Bg[(size_t)(n0 + lrow + it*32)*DD + lcol];
    }

    for (int k0 = 0; k0 < DD; k0 += 32) {
        __syncthreads();
        #pragma unroll
        for (int it = 0; it < 4; it++) {
            int r = lrow + it*32;
            As[r*SPITCH + lcol + 0] = f2tf(pa[it].x);
            As[r*SPITCH + lcol + 1] = f2tf(pa[it].y);
            As[r*SPITCH + lcol + 2] = f2tf(pa[it].z);
            As[r*SPITCH + lcol + 3] = f2tf(pa[it].w);
            Bs[r*SPITCH + lcol + 0] = f2tf(pb[it].x);
            Bs[r*SPITCH + lcol + 1] = f2tf(pb[it].y);
            Bs[r*SPITCH + lcol + 2] = f2tf(pb[it].z);
            Bs[r*SPITCH + lcol + 3] = f2tf(pb[it].w);
        }
        __syncthreads();

        if (k0 + 32 < DD) {
            #pragma unroll
            for (int it = 0; it < 4; it++) {
                pa[it] = *(const float4*)&Ag[(size_t)(m0 + lrow + it*32)*DD + k0 + 32 + lcol];
                pb[it] = *(const float4*)&Bg[(size_t)(n0 + lrow + it*32)*DD + k0 + 32 + lcol];
            }
        }

        #pragma unroll
        for (int k8 = 0; k8 < 4; k8++) {
            int kc = k8*8 + tig;
            unsigned a[4][4], b[4][2];
            #pragma unroll
            for (int mf = 0; mf < 4; mf++) {
                int r = wm*64 + mf*16 + gid;
                a[mf][0] = As[r*SPITCH + kc];
                a[mf][1] = As[(r+8)*SPITCH + kc];
                a[mf][2] = As[r*SPITCH + kc + 4];
                a[mf][3] = As[(r+8)*SPITCH + kc + 4];
            }
            #pragma unroll
            for (int nf = 0; nf < 4; nf++) {
                int n = wn*32 + nf*8 + gid;
                b[nf][0] = Bs[n*SPITCH + kc];
                b[nf][1] = Bs[n*SPITCH + kc + 4];
            }
            #pragma unroll
            for (int mf = 0; mf < 4; mf++)
                #pragma unroll
                for (int nf = 0; nf < 4; nf++)
                    mma_tf32(acc[mf*4 + nf], a[mf], b[nf]);
        }
    }
}

// ---------------------------------------------------------------------------
// Kernel 1: fused QKV projection (tf32 tensor cores).
// ---------------------------------------------------------------------------
__global__ __launch_bounds__(256) void qkv_gemm(
    const float* __restrict__ y,
    const float* __restrict__ Wq, const float* __restrict__ bq,
    const float* __restrict__ Wk, const float* __restrict__ bk,
    const float* __restrict__ Wv, const float* __restrict__ bv)
{
    __shared__ __align__(16) unsigned As[128*SPITCH];
    __shared__ __align__(16) unsigned Bs[128*SPITCH];

    int bn = blockIdx.x;
    int m0 = blockIdx.y * 128;
    int which = bn >> 3;
    const float* W; const float* bias; float* out;
    if (which == 0)      { W = Wq; bias = bq; out = g_q; }
    else if (which == 1) { W = Wk; bias = bk; out = g_k; }
    else                 { W = Wv; bias = bv; out = g_v; }
    int n0 = (bn & 7) * 128;

    int tid = threadIdx.x;
    float acc[16][4];
    #pragma unroll
    for (int i = 0; i < 16; i++)
        #pragma unroll
        for (int j = 0; j < 4; j++) acc[i][j] = 0.f;

    gemm_tf32_main(y, W, m0, n0, tid, As, Bs, acc);

    int lane = tid & 31, gid = lane >> 2, tig = lane & 3;
    int warp = tid >> 5, wm = warp & 1, wn = warp >> 1;

    #pragma unroll
    for (int mf = 0; mf < 4; mf++) {
        #pragma unroll
        for (int nf = 0; nf < 4; nf++) {
            float* c = acc[mf*4 + nf];
            int n = n0 + wn*32 + nf*8 + 2*tig;
            int h = n >> 6, hd = n & 63;
            float bx = bias[n], by = bias[n+1];
            int m = m0 + wm*64 + mf*16 + gid;
            int bi = m >> 10, s = m & 1023;
            float2 v0 = make_float2(c[0] + bx, c[1] + by);
            *(float2*)&out[(((size_t)(bi*HH + h))*SS + s)*HDIM + hd] = v0;
            m += 8; bi = m >> 10; s = m & 1023;
            float2 v1 = make_float2(c[2] + bx, c[3] + by);
            *(float2*)&out[(((size_t)(bi*HH + h))*SS + s)*HDIM + hd] = v1;
        }
    }
}

// ---------------------------------------------------------------------------
// Kernel 3: output projection + residual (tf32).  g_x = att @ Wm^T + bm + y
// ---------------------------------------------------------------------------
__global__ __launch_bounds__(256) void proj_gemm(
    const float* __restrict__ Wm, const float* __restrict__ bm,
    const float* __restrict__ y)
{
    __shared__ __align__(16) unsigned As[128*SPITCH];
    __shared__ __align__(16) unsigned Bs[128*SPITCH];

    int n0 = blockIdx.x * 128;
    int m0 = blockIdx.y * 128;
    int tid = threadIdx.x;

    float acc[16][4];
    #pragma unroll
    for (int i = 0; i < 16; i++)
        #pragma unroll
        for (int j = 0; j < 4; j++) acc[i][j] = 0.f;

    gemm_tf32_main(g_att, Wm, m0, n0, tid, As, Bs, acc);

    int lane = tid & 31, gid = lane >> 2, tig = lane & 3;
    int warp = tid >> 5, wm = warp & 1, wn = warp >> 1;

    #pragma unroll
    for (int mf = 0; mf < 4; mf++) {
        #pragma unroll
        for (int nf = 0; nf < 4; nf++) {
            float* c = acc[mf*4 + nf];
            int n = n0 + wn*32 + nf*8 + 2*tig;
            float bx = bm[n], by = bm[n+1];
            int m = m0 + wm*64 + mf*16 + gid;
            size_t o = (size_t)m*DD + n;
            float2 r0 = *(const float2*)&y[o];
            *(float2*)&g_x[o] = make_float2(c[0] + bx + r0.x, c[1] + by + r0.y);
            o += (size_t)8*DD;
            float2 r1 = *(const float2*)&y[o];
            *(float2*)&g_x[o] = make_float2(c[2] + bx + r1.x, c[3] + by + r1.y);
        }
    }
}

// ---------------------------------------------------------------------------
// Kernel 2: tf32 mma flash attention.
// Block = (qt, h, b): 64 q-rows, 128 threads = 4 warps; warp w owns rows
// w*16..w*16+15 exclusively -> softmax reductions stay inside each quad.
// K smem pitch 68 (bank = 4*gid+tig bijective), V pitch 72 (8*tig+gid).
// Q fragments register-resident across all 16 KV tiles.
// P accumulator-layout -> A-layout via quad shuffles (no smem round trip).
// ---------------------------------------------------------------------------
#define KP 68
#define VP 72

__global__ __launch_bounds__(128) void attn_mma(const int* __restrict__ mask)
{
    __shared__ __align__(16) unsigned Ks[64*KP];
    __shared__ __align__(16) unsigned Vs[64*VP];
    __shared__ int Ms[64];

    int qt = blockIdx.x, h = blockIdx.y, b = blockIdx.z;
    int tid = threadIdx.x;
    int lane = tid & 31, w = tid >> 5;
    int gid = lane >> 2, tig = lane & 3;

    const float* Q  = g_q + ((size_t)(b*HH + h)*SS + qt*64) * HDIM;
    const float* K0 = g_k + ((size_t)(b*HH + h)*SS) * HDIM;
    const float* V0 = g_v + ((size_t)(b*HH + h)*SS) * HDIM;

    // Q fragments for this warp's 16 rows (reused across all KV tiles).
    unsigned qa[8][4];
    {
        const float* Qw = Q + (w*16 + gid)*HDIM;
        #pragma unroll
        for (int s = 0; s < 8; s++) {
            qa[s][0] = f2tf(Qw[8*s + tig]);
            qa[s][1] = f2tf(Qw[8*HDIM + 8*s + tig]);
            qa[s][2] = f2tf(Qw[8*s + tig + 4]);
            qa[s][3] = f2tf(Qw[8*HDIM + 8*s + tig + 4]);
        }
    }

    float oa[8][4];
    #pragma unroll
    for (int i = 0; i < 8; i++)
        #pragma unroll
        for (int j = 0; j < 4; j++) oa[i][j] = 0.f;
    float mrow0 = -3.0e38f, mrow1 = -3.0e38f, lrow0 = 0.f, lrow1 = 0.f;

    for (int t = 0; t < 16; t++) {
        const float* K = K0 + (size_t)t*64*HDIM;
        const float* V = V0 + (size_t)t*64*HDIM;
        __syncthreads();   // previous tile's mma reads done
        #pragma unroll
        for (int it = 0; it < 8; it++) {
            int idx = tid + it*128;          // 0..1023 float4 slots
            int r = idx >> 4, c = (idx & 15) * 4;
            float4 k4 = *(const float4*)(K + r*HDIM + c);
            uint4 ku = make_uint4(f2tf(k4.x), f2tf(k4.y), f2tf(k4.z), f2tf(k4.w));
            *(uint4*)&Ks[r*KP + c] = ku;
            float4 v4 = *(const float4*)(V + r*HDIM + c);
            uint4 vu = make_uint4(f2tf(v4.x), f2tf(v4.y), f2tf(v4.z), f2tf(v4.w));
            *(uint4*)&Vs[r*VP + c] = vu;
        }
        if (tid < 16) {
            int4 m4 = *(const int4*)(mask + b*SS + t*64 + tid*4);
            Ms[tid*4 + 0] = m4.x; Ms[tid*4 + 1] = m4.y;
            Ms[tid*4 + 2] = m4.z; Ms[tid*4 + 3] = m4.w;
        }
        __syncthreads();

        // S = Q @ K^T  (16 rows x 64 keys per warp)
        float sf[8][4];
        #pragma unroll
        for (int i = 0; i < 8; i++)
            #pragma unroll
            for (int j = 0; j < 4; j++) sf[i][j] = 0.f;
        #pragma unroll
        for (int s = 0; s < 8; s++) {
            #pragma unroll
            for (int nf = 0; nf < 8; nf++) {
                unsigned bfr[2];
                bfr[0] = Ks[(nf*8 + gid)*KP + 8*s + tig];
                bfr[1] = Ks[(nf*8 + gid)*KP + 8*s + tig + 4];
                mma_tf32(sf[nf], qa[s], bfr);
            }
        }

        // mask (exact -1e9) + 1/sqrt(64) scale
        #pragma unroll
        for (int nf = 0; nf < 8; nf++) {
            int c0 = nf*8 + 2*tig;
            bool km0 = Ms[c0] != 0;
            bool km1 = Ms[c0 + 1] != 0;
            sf[nf][0] = km0 ? -1e9f : sf[nf][0]*0.125f;
            sf[nf][2] = km0 ? -1e9f : sf[nf][2]*0.125f;
            sf[nf][1] = km1 ? -1e9f : sf[nf][1]*0.125f;
            sf[nf][3] = km1 ? -1e9f : sf[nf][3]*0.125f;
        }

        // online softmax: rows r0=gid (slots 0,1), r1=gid+8 (slots 2,3)
        float tm0 = -3.0e38f, tm1 = -3.0e38f;
        #pragma unroll
        for (int nf = 0; nf < 8; nf++) {
            tm0 = fmaxf(tm0, fmaxf(sf[nf][0], sf[nf][1]));
            tm1 = fmaxf(tm1, fmaxf(sf[nf][2], sf[nf][3]));
        }
        tm0 = fmaxf(tm0, __shfl_xor_sync(0xffffffffu, tm0, 1));
        tm0 = fmaxf(tm0, __shfl_xor_sync(0xffffffffu, tm0, 2));
        tm1 = fmaxf(tm1, __shfl_xor_sync(0xffffffffu, tm1, 1));
        tm1 = fmaxf(tm1, __shfl_xor_sync(0xffffffffu, tm1, 2));

        float mn0 = fmaxf(mrow0, tm0), mn1 = fmaxf(mrow1, tm1);
        float al0 = __expf(mrow0 - mn0), al1 = __expf(mrow1 - mn1);
        float ps0 = 0.f, ps1 = 0.f;
        #pragma unroll
        for (int nf = 0; nf < 8; nf++) {
            sf[nf][0] = __expf(sf[nf][0] - mn0);
            sf[nf][1] = __expf(sf[nf][1] - mn0);
            sf[nf][2] = __expf(sf[nf][2] - mn1);
            sf[nf][3] = __expf(sf[nf][3] - mn1);
            ps0 += sf[nf][0] + sf[nf][1];
            ps1 += sf[nf][2] + sf[nf][3];
        }
        ps0 += __shfl_xor_sync(0xffffffffu, ps0, 1);
        ps0 += __shfl_xor_sync(0xffffffffu, ps0, 2);
        ps1 += __shfl_xor_sync(0xffffffffu, ps1, 1);
        ps1 += __shfl_xor_sync(0xffffffffu, ps1, 2);
        lrow0 = lrow0*al0 + ps0;  mrow0 = mn0;
        lrow1 = lrow1*al1 + ps1;  mrow1 = mn1;
        #pragma unroll
        for (int nf = 0; nf < 8; nf++) {
            oa[nf][0] *= al0; oa[nf][1] *= al0;
            oa[nf][2] *= al1; oa[nf][3] *= al1;
        }

        // O += P @ V : permute P (c-layout) -> A-layout per k-step via shfl
        int l0 = (lane & ~3) | (tig >> 1);
        int l1 = l0 + 2;
        bool odd = (tig & 1);
        #pragma unroll
        for (int s = 0; s < 8; s++) {
            float v00 = __shfl_sync(0xffffffffu, sf[s][0], l0);
            float v01 = __shfl_sync(0xffffffffu, sf[s][1], l0);
            float v20 = __shfl_sync(0xffffffffu, sf[s][2], l0);
            float v21 = __shfl_sync(0xffffffffu, sf[s][3], l0);
            float w00 = __shfl_sync(0xffffffffu, sf[s][0], l1);
            float w01 = __shfl_sync(0xffffffffu, sf[s][1], l1);
            float w20 = __shfl_sync(0xffffffffu, sf[s][2], l1);
            float w21 = __shfl_sync(0xffffffffu, sf[s][3], l1);
            unsigned pa[4];
            pa[0] = f2tf(odd ? v01 : v00);   // P[r0][8s+tig]
            pa[1] = f2tf(odd ? v21 : v20);   // P[r1][8s+tig]
            pa[2] = f2tf(odd ? w01 : w00);   // P[r0][8s+tig+4]
            pa[3] = f2tf(odd ? w21 : w20);   // P[r1][8s+tig+4]
            #pragma unroll
            for (int nf = 0; nf < 8; nf++) {
                unsigned bfr[2];
                bfr[0] = Vs[(8*s + tig)*VP + nf*8 + gid];
                bfr[1] = Vs[(8*s + tig + 4)*VP + nf*8 + gid];
                mma_tf32(oa[nf], pa, bfr);
            }
        }
    }

    // epilogue: normalize, write [B,S,D]
    float inv0 = 1.f / lrow0, inv1 = 1.f / lrow1;
    int r0 = qt*64 + w*16 + gid;
    #pragma unroll
    for (int nf = 0; nf < 8; nf++) {
        int col = h*HDIM + nf*8 + 2*tig;
        *(float2*)&g_att[((size_t)(b*SS + r0))*DD + col] =
            make_float2(oa[nf][0]*inv0, oa[nf][1]*inv0);
        *(float2*)&g_att[((size_t)(b*SS + r0 + 8))*DD + col] =
            make_float2(oa[nf][2]*inv1, oa[nf][3]*inv1);
    }
}

// ---------------------------------------------------------------------------
// Kernel 4: LayerNorm (torch semantics: unbiased std, eps added to std).
// ---------------------------------------------------------------------------
__global__ __launch_bounds__(256) void ln_kernel(
    const float* __restrict__ a2, const float* __restrict__ b2,
    float* __restrict__ out)
{
    __shared__ float ws[8];
    int row = blockIdx.x;
    int tid = threadIdx.x;
    int lane = tid & 31, wid = tid >> 5;

    const float* x = g_x + (size_t)row * DD;
    float4 v = *(const float4*)(x + tid*4);

    float s = v.x + v.y + v.z + v.w;
    #pragma unroll
    for (int m = 16; m; m >>= 1) s += __shfl_xor_sync(0xffffffffu, s, m);
    if (lane == 0) ws[wid] = s;
    __syncthreads();
    float tot = 0.f;
    #pragma unroll
    for (int i = 0; i < 8; i++) tot += ws[i];
    float mean = tot * (1.f / 1024.f);
    __syncthreads();

    float d0 = v.x - mean, d1 = v.y - mean, d2 = v.z - mean, d3 = v.w - mean;
    float ss = d0*d0 + d1*d1 + d2*d2 + d3*d3;
    #pragma unroll
    for (int m = 16; m; m >>= 1) ss += __shfl_xor_sync(0xffffffffu, ss, m);
    if (lane == 0) ws[wid] = ss;
    __syncthreads();
    float sst = 0.f;
    #pragma unroll
    for (int i = 0; i < 8; i++) sst += ws[i];

    float stdv = sqrtf(sst * (1.f / 1023.f));   // ddof = 1
    float inv = 1.f / (stdv + 1e-6f);           // eps on std

    float4 a = *(const float4*)(a2 + tid*4);
    float4 bb = *(const float4*)(b2 + tid*4);
    float4 o;
    o.x = a.x * d0 * inv + bb.x;
    o.y = a.y * d1 * inv + bb.y;
    o.z = a.z * d2 * inv + bb.z;
    o.w = a.w * d3 * inv + bb.w;
    *(float4*)(out + (size_t)row * DD + tid*4) = o;
}

// ---------------------------------------------------------------------------
// Launch
// ---------------------------------------------------------------------------
extern "C" void kernel_launch(void* const* d_in, const int* in_sizes, int n_in,
                              void* d_out, int out_size)
{
    (void)in_sizes; (void)n_in; (void)out_size;
    const float* y  = (const float*)d_in[0];
    const int* ym   = (const int*)d_in[1];    // jax bool materialized as int32
    const float* Wq = (const float*)d_in[2];
    const float* bq = (const float*)d_in[3];
    const float* Wk = (const float*)d_in[4];
    const float* bk = (const float*)d_in[5];
    const float* Wv = (const float*)d_in[6];
    const float* bv = (const float*)d_in[7];
    const float* Wm = (const float*)d_in[8];
    const float* bm = (const float*)d_in[9];
    const float* a2 = (const float*)d_in[10];
    const float* b2 = (const float*)d_in[11];
    float* out = (float*)d_out;

    qkv_gemm<<<dim3(24, 64), 256>>>(y, Wq, bq, Wk, bk, Wv, bv);
    attn_mma<<<dim3(16, 16, 8), 128>>>(ym);
    proj_gemm<<<dim3(8, 64), 256>>>(Wm, bm, y);
    ln_kernel<<<MR, 256>>>(a2, b2, out);
}

// round 9
// speedup vs baseline: 4.2776x; 1.2458x over previous
#include <cuda_runtime.h>
#include <cuda_bf16.h>
#include <math.h>

// Problem constants
#define BB   8
#define SS   1024
#define DD   1024
#define HH   16
#define HDIM 64
#define MR   (BB*SS)      // 8192 rows

// ---------------------------------------------------------------------------
// Scratch (device globals: allocation-free per harness rules)
// ---------------------------------------------------------------------------
__device__ float g_q[BB*HH*SS*HDIM];
__device__ float g_k[BB*HH*SS*HDIM];
__device__ float g_v[BB*HH*SS*HDIM];
__device__ float g_att[BB*SS*DD];
__device__ float g_x[BB*SS*DD];

// ---------------------------------------------------------------------------
// mma helpers
// ---------------------------------------------------------------------------
__device__ __forceinline__ unsigned f2tf(float f) {
    unsigned u;
    asm("cvt.rna.tf32.f32 %0, %1;" : "=r"(u) : "f"(f));
    return u;
}

__device__ __forceinline__ unsigned packbf(float lo, float hi) {
    unsigned u;
    asm("cvt.rn.bf16x2.f32 %0, %1, %2;" : "=r"(u) : "f"(hi), "f"(lo));
    return u;
}

__device__ __forceinline__ void mma_tf32(float* d, const unsigned* a, const unsigned* b) {
    asm volatile(
        "mma.sync.aligned.m16n8k8.row.col.f32.tf32.tf32.f32 "
        "{%0,%1,%2,%3}, {%4,%5,%6,%7}, {%8,%9}, {%0,%1,%2,%3};"
        : "+f"(d[0]), "+f"(d[1]), "+f"(d[2]), "+f"(d[3])
        : "r"(a[0]), "r"(a[1]), "r"(a[2]), "r"(a[3]),
          "r"(b[0]), "r"(b[1]));
}

__device__ __forceinline__ void mma_bf16(float* d, const unsigned* a, const unsigned* b) {
    asm volatile(
        "mma.sync.aligned.m16n8k16.row.col.f32.bf16.bf16.f32 "
        "{%0,%1,%2,%3}, {%4,%5,%6,%7}, {%8,%9}, {%0,%1,%2,%3};"
        : "+f"(d[0]), "+f"(d[1]), "+f"(d[2]), "+f"(d[3])
        : "r"(a[0]), "r"(a[1]), "r"(a[2]), "r"(a[3]),
          "r"(b[0]), "r"(b[1]));
}

// bf16 GEMM shared-tile pitch in u32 k-pairs: 16 pairs + 4 pad.
// Fragment address = row*20 + kpair -> bank (4*gid + tig) bijective: conflict-free.
#define BPITCH 20

// ---------------------------------------------------------------------------
// bf16 GEMM mainloop (qkv + proj kernels).  C = A @ B^T, 128x128 tile, K=1024.
// A,B row-major fp32 [*,1024]; converted to packed bf16x2 at smem store.
// Warp tile 64x32, mma m16n8k16, 2 k16-steps per 32-wide K slab.
// ---------------------------------------------------------------------------
__device__ __forceinline__ void gemm_bf16_main(
    const float* __restrict__ Ag, const float* __restrict__ Bg,
    int m0, int n0, int tid,
    unsigned* As, unsigned* Bs, float acc[16][4])
{
    int lane = tid & 31, gid = lane >> 2, tig = lane & 3;
    int warp = tid >> 5, wm = warp & 1, wn = warp >> 1;

    int lrow  = tid >> 3;           // 0..31
    int lcol  = (tid & 7) * 4;      // float index 0,4,...,28
    int lcolp = (tid & 7) * 2;      // k-pair index 0,2,...,14

    float4 pa[4], pb[4];
    #pragma unroll
    for (int it = 0; it < 4; it++) {
        pa[it] = *(const float4*)&Ag[(size_t)(m0 + lrow + it*32)*DD + lcol];
        pb[it] = *(const float4*)&Bg[(size_t)(n0 + lrow + it*32)*DD + lcol];
    }

    for (int k0 = 0; k0 < DD; k0 += 32) {
        __syncthreads();
        #pragma unroll
        for (int it = 0; it < 4; it++) {
            int r = lrow + it*32;
            uint2 ua = make_uint2(packbf(pa[it].x, pa[it].y), packbf(pa[it].z, pa[it].w));
            *(uint2*)&As[r*BPITCH + lcolp] = ua;
            uint2 ub = make_uint2(packbf(pb[it].x, pb[it].y), packbf(pb[it].z, pb[it].w));
            *(uint2*)&Bs[r*BPITCH + lcolp] = ub;
        }
        __syncthreads();

        if (k0 + 32 < DD) {
            #pragma unroll
            for (int it = 0; it < 4; it++) {
                pa[it] = *(const float4*)&Ag[(size_t)(m0 + lrow + it*32)*DD + k0 + 32 + lcol];
                pb[it] = *(const float4*)&Bg[(size_t)(n0 + lrow + it*32)*DD + k0 + 32 + lcol];
            }
        }

        // two m16n8k16 steps cover the 32-wide K slab (k-pairs 0..7, 8..15)
        #pragma unroll
        for (int kp = 0; kp < 16; kp += 8) {
            int kc = kp + tig;
            unsigned a[4][4], b[4][2];
            #pragma unroll
            for (int mf = 0; mf < 4; mf++) {
                int r = wm*64 + mf*16 + gid;
                a[mf][0] = As[r*BPITCH + kc];
                a[mf][1] = As[(r+8)*BPITCH + kc];
                a[mf][2] = As[r*BPITCH + kc + 4];
                a[mf][3] = As[(r+8)*BPITCH + kc + 4];
            }
            #pragma unroll
            for (int nf = 0; nf < 4; nf++) {
                int n = wn*32 + nf*8 + gid;
                b[nf][0] = Bs[n*BPITCH + kc];
                b[nf][1] = Bs[n*BPITCH + kc + 4];
            }
            #pragma unroll
            for (int mf = 0; mf < 4; mf++)
                #pragma unroll
                for (int nf = 0; nf < 4; nf++)
                    mma_bf16(acc[mf*4 + nf], a[mf], b[nf]);
        }
    }
}

// ---------------------------------------------------------------------------
// Kernel 1: fused QKV projection (bf16 tensor cores).
// grid.x = 24 (3 weights x 8 n-blocks), grid.y = 64 (m-blocks). 256 thr.
// ---------------------------------------------------------------------------
__global__ __launch_bounds__(256) void qkv_gemm(
    const float* __restrict__ y,
    const float* __restrict__ Wq, const float* __restrict__ bq,
    const float* __restrict__ Wk, const float* __restrict__ bk,
    const float* __restrict__ Wv, const float* __restrict__ bv)
{
    __shared__ __align__(16) unsigned As[128*BPITCH];
    __shared__ __align__(16) unsigned Bs[128*BPITCH];

    int bn = blockIdx.x;
    int m0 = blockIdx.y * 128;
    int which = bn >> 3;
    const float* W; const float* bias; float* out;
    if (which == 0)      { W = Wq; bias = bq; out = g_q; }
    else if (which == 1) { W = Wk; bias = bk; out = g_k; }
    else                 { W = Wv; bias = bv; out = g_v; }
    int n0 = (bn & 7) * 128;

    int tid = threadIdx.x;
    float acc[16][4];
    #pragma unroll
    for (int i = 0; i < 16; i++)
        #pragma unroll
        for (int j = 0; j < 4; j++) acc[i][j] = 0.f;

    gemm_bf16_main(y, W, m0, n0, tid, As, Bs, acc);

    int lane = tid & 31, gid = lane >> 2, tig = lane & 3;
    int warp = tid >> 5, wm = warp & 1, wn = warp >> 1;

    #pragma unroll
    for (int mf = 0; mf < 4; mf++) {
        #pragma unroll
        for (int nf = 0; nf < 4; nf++) {
            float* c = acc[mf*4 + nf];
            int n = n0 + wn*32 + nf*8 + 2*tig;
            int h = n >> 6, hd = n & 63;
            float bx = bias[n], by = bias[n+1];
            int m = m0 + wm*64 + mf*16 + gid;
            int bi = m >> 10, s = m & 1023;
            float2 v0 = make_float2(c[0] + bx, c[1] + by);
            *(float2*)&out[(((size_t)(bi*HH + h))*SS + s)*HDIM + hd] = v0;
            m += 8; bi = m >> 10; s = m & 1023;
            float2 v1 = make_float2(c[2] + bx, c[3] + by);
            *(float2*)&out[(((size_t)(bi*HH + h))*SS + s)*HDIM + hd] = v1;
        }
    }
}

// ---------------------------------------------------------------------------
// Kernel 3: output projection + residual (bf16).  g_x = att @ Wm^T + bm + y
// ---------------------------------------------------------------------------
__global__ __launch_bounds__(256) void proj_gemm(
    const float* __restrict__ Wm, const float* __restrict__ bm,
    const float* __restrict__ y)
{
    __shared__ __align__(16) unsigned As[128*BPITCH];
    __shared__ __align__(16) unsigned Bs[128*BPITCH];

    int n0 = blockIdx.x * 128;
    int m0 = blockIdx.y * 128;
    int tid = threadIdx.x;

    float acc[16][4];
    #pragma unroll
    for (int i = 0; i < 16; i++)
        #pragma unroll
        for (int j = 0; j < 4; j++) acc[i][j] = 0.f;

    gemm_bf16_main(g_att, Wm, m0, n0, tid, As, Bs, acc);

    int lane = tid & 31, gid = lane >> 2, tig = lane & 3;
    int warp = tid >> 5, wm = warp & 1, wn = warp >> 1;

    #pragma unroll
    for (int mf = 0; mf < 4; mf++) {
        #pragma unroll
        for (int nf = 0; nf < 4; nf++) {
            float* c = acc[mf*4 + nf];
            int n = n0 + wn*32 + nf*8 + 2*tig;
            float bx = bm[n], by = bm[n+1];
            int m = m0 + wm*64 + mf*16 + gid;
            size_t o = (size_t)m*DD + n;
            float2 r0 = *(const float2*)&y[o];
            *(float2*)&g_x[o] = make_float2(c[0] + bx + r0.x, c[1] + by + r0.y);
            o += (size_t)8*DD;
            float2 r1 = *(const float2*)&y[o];
            *(float2*)&g_x[o] = make_float2(c[2] + bx + r1.x, c[3] + by + r1.y);
        }
    }
}

// ---------------------------------------------------------------------------
// Kernel 2: tf32 mma flash attention.  (Measured 4.1x win in R8 — unchanged.)
// ---------------------------------------------------------------------------
#define KP 68
#define VP 72

__global__ __launch_bounds__(128) void attn_mma(const int* __restrict__ mask)
{
    __shared__ __align__(16) unsigned Ks[64*KP];
    __shared__ __align__(16) unsigned Vs[64*VP];
    __shared__ int Ms[64];

    int qt = blockIdx.x, h = blockIdx.y, b = blockIdx.z;
    int tid = threadIdx.x;
    int lane = tid & 31, w = tid >> 5;
    int gid = lane >> 2, tig = lane & 3;

    const float* Q  = g_q + ((size_t)(b*HH + h)*SS + qt*64) * HDIM;
    const float* K0 = g_k + ((size_t)(b*HH + h)*SS) * HDIM;
    const float* V0 = g_v + ((size_t)(b*HH + h)*SS) * HDIM;

    // Q fragments for this warp's 16 rows (reused across all KV tiles).
    unsigned qa[8][4];
    {
        const float* Qw = Q + (w*16 + gid)*HDIM;
        #pragma unroll
        for (int s = 0; s < 8; s++) {
            qa[s][0] = f2tf(Qw[8*s + tig]);
            qa[s][1] = f2tf(Qw[8*HDIM + 8*s + tig]);
            qa[s][2] = f2tf(Qw[8*s + tig + 4]);
            qa[s][3] = f2tf(Qw[8*HDIM + 8*s + tig + 4]);
        }
    }

    float oa[8][4];
    #pragma unroll
    for (int i = 0; i < 8; i++)
        #pragma unroll
        for (int j = 0; j < 4; j++) oa[i][j] = 0.f;
    float mrow0 = -3.0e38f, mrow1 = -3.0e38f, lrow0 = 0.f, lrow1 = 0.f;

    for (int t = 0; t < 16; t++) {
        const float* K = K0 + (size_t)t*64*HDIM;
        const float* V = V0 + (size_t)t*64*HDIM;
        __syncthreads();   // previous tile's mma reads done
        #pragma unroll
        for (int it = 0; it < 8; it++) {
            int idx = tid + it*128;          // 0..1023 float4 slots
            int r = idx >> 4, c = (idx & 15) * 4;
            float4 k4 = *(const float4*)(K + r*HDIM + c);
            uint4 ku = make_uint4(f2tf(k4.x), f2tf(k4.y), f2tf(k4.z), f2tf(k4.w));
            *(uint4*)&Ks[r*KP + c] = ku;
            float4 v4 = *(const float4*)(V + r*HDIM + c);
            uint4 vu = make_uint4(f2tf(v4.x), f2tf(v4.y), f2tf(v4.z), f2tf(v4.w));
            *(uint4*)&Vs[r*VP + c] = vu;
        }
        if (tid < 16) {
            int4 m4 = *(const int4*)(mask + b*SS + t*64 + tid*4);
            Ms[tid*4 + 0] = m4.x; Ms[tid*4 + 1] = m4.y;
            Ms[tid*4 + 2] = m4.z; Ms[tid*4 + 3] = m4.w;
        }
        __syncthreads();

        // S = Q @ K^T  (16 rows x 64 keys per warp)
        float sf[8][4];
        #pragma unroll
        for (int i = 0; i < 8; i++)
            #pragma unroll
            for (int j = 0; j < 4; j++) sf[i][j] = 0.f;
        #pragma unroll
        for (int s = 0; s < 8; s++) {
            #pragma unroll
            for (int nf = 0; nf < 8; nf++) {
                unsigned bfr[2];
                bfr[0] = Ks[(nf*8 + gid)*KP + 8*s + tig];
                bfr[1] = Ks[(nf*8 + gid)*KP + 8*s + tig + 4];
                mma_tf32(sf[nf], qa[s], bfr);
            }
        }

        // mask (exact -1e9) + 1/sqrt(64) scale
        #pragma unroll
        for (int nf = 0; nf < 8; nf++) {
            int c0 = nf*8 + 2*tig;
            bool km0 = Ms[c0] != 0;
            bool km1 = Ms[c0 + 1] != 0;
            sf[nf][0] = km0 ? -1e9f : sf[nf][0]*0.125f;
            sf[nf][2] = km0 ? -1e9f : sf[nf][2]*0.125f;
            sf[nf][1] = km1 ? -1e9f : sf[nf][1]*0.125f;
            sf[nf][3] = km1 ? -1e9f : sf[nf][3]*0.125f;
        }

        // online softmax: rows r0=gid (slots 0,1), r1=gid+8 (slots 2,3)
        float tm0 = -3.0e38f, tm1 = -3.0e38f;
        #pragma unroll
        for (int nf = 0; nf < 8; nf++) {
            tm0 = fmaxf(tm0, fmaxf(sf[nf][0], sf[nf][1]));
            tm1 = fmaxf(tm1, fmaxf(sf[nf][2], sf[nf][3]));
        }
        tm0 = fmaxf(tm0, __shfl_xor_sync(0xffffffffu, tm0, 1));
        tm0 = fmaxf(tm0, __shfl_xor_sync(0xffffffffu, tm0, 2));
        tm1 = fmaxf(tm1, __shfl_xor_sync(0xffffffffu, tm1, 1));
        tm1 = fmaxf(tm1, __shfl_xor_sync(0xffffffffu, tm1, 2));

        float mn0 = fmaxf(mrow0, tm0), mn1 = fmaxf(mrow1, tm1);
        float al0 = __expf(mrow0 - mn0), al1 = __expf(mrow1 - mn1);
        float ps0 = 0.f, ps1 = 0.f;
        #pragma unroll
        for (int nf = 0; nf < 8; nf++) {
            sf[nf][0] = __expf(sf[nf][0] - mn0);
            sf[nf][1] = __expf(sf[nf][1] - mn0);
            sf[nf][2] = __expf(sf[nf][2] - mn1);
            sf[nf][3] = __expf(sf[nf][3] - mn1);
            ps0 += sf[nf][0] + sf[nf][1];
            ps1 += sf[nf][2] + sf[nf][3];
        }
        ps0 += __shfl_xor_sync(0xffffffffu, ps0, 1);
        ps0 += __shfl_xor_sync(0xffffffffu, ps0, 2);
        ps1 += __shfl_xor_sync(0xffffffffu, ps1, 1);
        ps1 += __shfl_xor_sync(0xffffffffu, ps1, 2);
        lrow0 = lrow0*al0 + ps0;  mrow0 = mn0;
        lrow1 = lrow1*al1 + ps1;  mrow1 = mn1;
        #pragma unroll
        for (int nf = 0; nf < 8; nf++) {
            oa[nf][0] *= al0; oa[nf][1] *= al0;
            oa[nf][2] *= al1; oa[nf][3] *= al1;
        }

        // O += P @ V : permute P (c-layout) -> A-layout per k-step via shfl
        int l0 = (lane & ~3) | (tig >> 1);
        int l1 = l0 + 2;
        bool odd = (tig & 1);
        #pragma unroll
        for (int s = 0; s < 8; s++) {
            float v00 = __shfl_sync(0xffffffffu, sf[s][0], l0);
            float v01 = __shfl_sync(0xffffffffu, sf[s][1], l0);
            float v20 = __shfl_sync(0xffffffffu, sf[s][2], l0);
            float v21 = __shfl_sync(0xffffffffu, sf[s][3], l0);
            float w00 = __shfl_sync(0xffffffffu, sf[s][0], l1);
            float w01 = __shfl_sync(0xffffffffu, sf[s][1], l1);
            float w20 = __shfl_sync(0xffffffffu, sf[s][2], l1);
            float w21 = __shfl_sync(0xffffffffu, sf[s][3], l1);
            unsigned pa[4];
            pa[0] = f2tf(odd ? v01 : v00);   // P[r0][8s+tig]
            pa[1] = f2tf(odd ? v21 : v20);   // P[r1][8s+tig]
            pa[2] = f2tf(odd ? w01 : w00);   // P[r0][8s+tig+4]
            pa[3] = f2tf(odd ? w21 : w20);   // P[r1][8s+tig+4]
            #pragma unroll
            for (int nf = 0; nf < 8; nf++) {
                unsigned bfr[2];
                bfr[0] = Vs[(8*s + tig)*VP + nf*8 + gid];
                bfr[1] = Vs[(8*s + tig + 4)*VP + nf*8 + gid];
                mma_tf32(oa[nf], pa, bfr);
            }
        }
    }

    // epilogue: normalize, write [B,S,D]
    float inv0 = 1.f / lrow0, inv1 = 1.f / lrow1;
    int r0 = qt*64 + w*16 + gid;
    #pragma unroll
    for (int nf = 0; nf < 8; nf++) {
        int col = h*HDIM + nf*8 + 2*tig;
        *(float2*)&g_att[((size_t)(b*SS + r0))*DD + col] =
            make_float2(oa[nf][0]*inv0, oa[nf][1]*inv0);
        *(float2*)&g_att[((size_t)(b*SS + r0 + 8))*DD + col] =
            make_float2(oa[nf][2]*inv1, oa[nf][3]*inv1);
    }
}

// ---------------------------------------------------------------------------
// Kernel 4: LayerNorm (torch semantics: unbiased std, eps added to std).
// ---------------------------------------------------------------------------
__global__ __launch_bounds__(256) void ln_kernel(
    const float* __restrict__ a2, const float* __restrict__ b2,
    float* __restrict__ out)
{
    __shared__ float ws[8];
    int row = blockIdx.x;
    int tid = threadIdx.x;
    int lane = tid & 31, wid = tid >> 5;

    const float* x = g_x + (size_t)row * DD;
    float4 v = *(const float4*)(x + tid*4);

    float s = v.x + v.y + v.z + v.w;
    #pragma unroll
    for (int m = 16; m; m >>= 1) s += __shfl_xor_sync(0xffffffffu, s, m);
    if (lane == 0) ws[wid] = s;
    __syncthreads();
    float tot = 0.f;
    #pragma unroll
    for (int i = 0; i < 8; i++) tot += ws[i];
    float mean = tot * (1.f / 1024.f);
    __syncthreads();

    float d0 = v.x - mean, d1 = v.y - mean, d2 = v.z - mean, d3 = v.w - mean;
    float ss = d0*d0 + d1*d1 + d2*d2 + d3*d3;
    #pragma unroll
    for (int m = 16; m; m >>= 1) ss += __shfl_xor_sync(0xffffffffu, ss, m);
    if (lane == 0) ws[wid] = ss;
    __syncthreads();
    float sst = 0.f;
    #pragma unroll
    for (int i = 0; i < 8; i++) sst += ws[i];

    float stdv = sqrtf(sst * (1.f / 1023.f));   // ddof = 1
    float inv = 1.f / (stdv + 1e-6f);           // eps on std

    float4 a = *(const float4*)(a2 + tid*4);
    float4 bb = *(const float4*)(b2 + tid*4);
    float4 o;
    o.x = a.x * d0 * inv + bb.x;
    o.y = a.y * d1 * inv + bb.y;
    o.z = a.z * d2 * inv + bb.z;
    o.w = a.w * d3 * inv + bb.w;
    *(float4*)(out + (size_t)row * DD + tid*4) = o;
}

// ---------------------------------------------------------------------------
// Launch
// ---------------------------------------------------------------------------
extern "C" void kernel_launch(void* const* d_in, const int* in_sizes, int n_in,
                              void* d_out, int out_size)
{
    (void)in_sizes; (void)n_in; (void)out_size;
    const float* y  = (const float*)d_in[0];
    const int* ym   = (const int*)d_in[1];    // jax bool materialized as int32
    const float* Wq = (const float*)d_in[2];
    const float* bq = (const float*)d_in[3];
    const float* Wk = (const float*)d_in[4];
    const float* bk = (const float*)d_in[5];
    const float* Wv = (const float*)d_in[6];
    const float* bv = (const float*)d_in[7];
    const float* Wm = (const float*)d_in[8];
    const float* bm = (const float*)d_in[9];
    const float* a2 = (const float*)d_in[10];
    const float* b2 = (const float*)d_in[11];
    float* out = (float*)d_out;

    qkv_gemm<<<dim3(24, 64), 256>>>(y, Wq, bq, Wk, bk, Wv, bv);
    attn_mma<<<dim3(16, 16, 8), 128>>>(ym);
    proj_gemm<<<dim3(8, 64), 256>>>(Wm, bm, y);
    ln_kernel<<<MR, 256>>>(a2, b2, out);
}

// round 12
// speedup vs baseline: 5.6434x; 1.3193x over previous
#include <cuda_runtime.h>
#include <cuda_bf16.h>
#include <math.h>

// Problem constants
#define BB   8
#define SS   1024
#define DD   1024
#define HH   16
#define HDIM 64
#define MR   (BB*SS)      // 8192 rows

// ---------------------------------------------------------------------------
// Scratch (device globals: allocation-free per harness rules)
// q,k: bf16 [B,H,S,HD].  v: bf16 TRANSPOSED [B,H,HD,S] (seq-pairs adjacent,
// so PV b-fragments pack directly).  att,x: fp32 [B,S,D].
// ---------------------------------------------------------------------------
__device__ __nv_bfloat16 g_qb[BB*HH*SS*HDIM];
__device__ __nv_bfloat16 g_kb[BB*HH*SS*HDIM];
__device__ __nv_bfloat16 g_vb[BB*HH*HDIM*SS];
__device__ float g_att[BB*SS*DD];
__device__ float g_x[BB*SS*DD];

// ---------------------------------------------------------------------------
// mma helpers
// ---------------------------------------------------------------------------
__device__ __forceinline__ unsigned packbf(float lo, float hi) {
    unsigned u;
    asm("cvt.rn.bf16x2.f32 %0, %1, %2;" : "=r"(u) : "f"(hi), "f"(lo));
    return u;
}

__device__ __forceinline__ void mma_bf16(float* d, const unsigned* a, const unsigned* b) {
    asm volatile(
        "mma.sync.aligned.m16n8k16.row.col.f32.bf16.bf16.f32 "
        "{%0,%1,%2,%3}, {%4,%5,%6,%7}, {%8,%9}, {%0,%1,%2,%3};"
        : "+f"(d[0]), "+f"(d[1]), "+f"(d[2]), "+f"(d[3])
        : "r"(a[0]), "r"(a[1]), "r"(a[2]), "r"(a[3]),
          "r"(b[0]), "r"(b[1]));
}

// bf16 GEMM shared-tile pitch in u32 k-pairs: 16 pairs + 4 pad (conflict-free).
#define BPITCH 20

// ---------------------------------------------------------------------------
// bf16 GEMM mainloop.  C = A @ B^T, 128x128 tile, K=1024.  (Measured in R9.)
// ---------------------------------------------------------------------------
__device__ __forceinline__ void gemm_bf16_main(
    const float* __restrict__ Ag, const float* __restrict__ Bg,
    int m0, int n0, int tid,
    unsigned* As, unsigned* Bs, float acc[16][4])
{
    int lane = tid & 31, gid = lane >> 2, tig = lane & 3;
    int warp = tid >> 5, wm = warp & 1, wn = warp >> 1;

    int lrow  = tid >> 3;           // 0..31
    int lcol  = (tid & 7) * 4;      // float index
    int lcolp = (tid & 7) * 2;      // k-pair index

    float4 pa[4], pb[4];
    #pragma unroll
    for (int it = 0; it < 4; it++) {
        pa[it] = *(const float4*)&Ag[(size_t)(m0 + lrow + it*32)*DD + lcol];
        pb[it] = *(const float4*)&Bg[(size_t)(n0 + lrow + it*32)*DD + lcol];
    }

    for (int k0 = 0; k0 < DD; k0 += 32) {
        __syncthreads();
        #pragma unroll
        for (int it = 0; it < 4; it++) {
            int r = lrow + it*32;
            uint2 ua = make_uint2(packbf(pa[it].x, pa[it].y), packbf(pa[it].z, pa[it].w));
            *(uint2*)&As[r*BPITCH + lcolp] = ua;
            uint2 ub = make_uint2(packbf(pb[it].x, pb[it].y), packbf(pb[it].z, pb[it].w));
            *(uint2*)&Bs[r*BPITCH + lcolp] = ub;
        }
        __syncthreads();

        if (k0 + 32 < DD) {
            #pragma unroll
            for (int it = 0; it < 4; it++) {
                pa[it] = *(const float4*)&Ag[(size_t)(m0 + lrow + it*32)*DD + k0 + 32 + lcol];
                pb[it] = *(const float4*)&Bg[(size_t)(n0 + lrow + it*32)*DD + k0 + 32 + lcol];
            }
        }

        #pragma unroll
        for (int kp = 0; kp < 16; kp += 8) {
            int kc = kp + tig;
            unsigned a[4][4], b[4][2];
            #pragma unroll
            for (int mf = 0; mf < 4; mf++) {
                int r = wm*64 + mf*16 + gid;
                a[mf][0] = As[r*BPITCH + kc];
                a[mf][1] = As[(r+8)*BPITCH + kc];
                a[mf][2] = As[r*BPITCH + kc + 4];
                a[mf][3] = As[(r+8)*BPITCH + kc + 4];
            }
            #pragma unroll
            for (int nf = 0; nf < 4; nf++) {
                int n = wn*32 + nf*8 + gid;
                b[nf][0] = Bs[n*BPITCH + kc];
                b[nf][1] = Bs[n*BPITCH + kc + 4];
            }
            #pragma unroll
            for (int mf = 0; mf < 4; mf++)
                #pragma unroll
                for (int nf = 0; nf < 4; nf++)
                    mma_bf16(acc[mf*4 + nf], a[mf], b[nf]);
        }
    }
}

// ---------------------------------------------------------------------------
// Kernel 1: fused QKV projection (bf16 tensor cores); bf16 outputs.
// q/k -> [B,H,S,HD] (paired bf16x2 stores); v -> [B,H,HD,S] transposed.
// ---------------------------------------------------------------------------
__global__ __launch_bounds__(256) void qkv_gemm(
    const float* __restrict__ y,
    const float* __restrict__ Wq, const float* __restrict__ bq,
    const float* __restrict__ Wk, const float* __restrict__ bk,
    const float* __restrict__ Wv, const float* __restrict__ bv)
{
    __shared__ __align__(16) unsigned As[128*BPITCH];
    __shared__ __align__(16) unsigned Bs[128*BPITCH];

    int bn = blockIdx.x;
    int m0 = blockIdx.y * 128;
    int which = bn >> 3;
    const float* W; const float* bias;
    if (which == 0)      { W = Wq; bias = bq; }
    else if (which == 1) { W = Wk; bias = bk; }
    else                 { W = Wv; bias = bv; }
    int n0 = (bn & 7) * 128;

    int tid = threadIdx.x;
    float acc[16][4];
    #pragma unroll
    for (int i = 0; i < 16; i++)
        #pragma unroll
        for (int j = 0; j < 4; j++) acc[i][j] = 0.f;

    gemm_bf16_main(y, W, m0, n0, tid, As, Bs, acc);

    int lane = tid & 31, gid = lane >> 2, tig = lane & 3;
    int warp = tid >> 5, wm = warp & 1, wn = warp >> 1;

    if (which < 2) {
        __nv_bfloat16* ob = (which == 0) ? g_qb : g_kb;
        #pragma unroll
        for (int mf = 0; mf < 4; mf++) {
            #pragma unroll
            for (int nf = 0; nf < 4; nf++) {
                float* c = acc[mf*4 + nf];
                int n = n0 + wn*32 + nf*8 + 2*tig;
                int h = n >> 6, hd = n & 63;
                float bx = bias[n], by = bias[n+1];
                int m = m0 + wm*64 + mf*16 + gid;
                int bi = m >> 10, s = m & 1023;
                *(unsigned*)&ob[(((size_t)(bi*HH + h))*SS + s)*HDIM + hd] =
                    packbf(c[0] + bx, c[1] + by);
                m += 8; bi = m >> 10; s = m & 1023;
                *(unsigned*)&ob[(((size_t)(bi*HH + h))*SS + s)*HDIM + hd] =
                    packbf(c[2] + bx, c[3] + by);
            }
        }
    } else {
        #pragma unroll
        for (int mf = 0; mf < 4; mf++) {
            #pragma unroll
            for (int nf = 0; nf < 4; nf++) {
                float* c = acc[mf*4 + nf];
                int n = n0 + wn*32 + nf*8 + 2*tig;
                int h = n >> 6, hd = n & 63;
                float bx = bias[n], by = bias[n+1];
                int m = m0 + wm*64 + mf*16 + gid;
                int bi = m >> 10, s = m & 1023;           // m and m+8 share bi
                size_t vb = ((size_t)(bi*HH + h))*HDIM;
                g_vb[(vb + hd    )*SS + s    ] = __float2bfloat16_rn(c[0] + bx);
                g_vb[(vb + hd + 1)*SS + s    ] = __float2bfloat16_rn(c[1] + by);
                g_vb[(vb + hd    )*SS + s + 8] = __float2bfloat16_rn(c[2] + bx);
                g_vb[(vb + hd + 1)*SS + s + 8] = __float2bfloat16_rn(c[3] + by);
            }
        }
    }
}

// ---------------------------------------------------------------------------
// Kernel 3: output projection + residual (bf16).  g_x = att @ Wm^T + bm + y
// ---------------------------------------------------------------------------
__global__ __launch_bounds__(256) void proj_gemm(
    const float* __restrict__ Wm, const float* __restrict__ bm,
    const float* __restrict__ y)
{
    __shared__ __align__(16) unsigned As[128*BPITCH];
    __shared__ __align__(16) unsigned Bs[128*BPITCH];

    int n0 = blockIdx.x * 128;
    int m0 = blockIdx.y * 128;
    int tid = threadIdx.x;

    float acc[16][4];
    #pragma unroll
    for (int i = 0; i < 16; i++)
        #pragma unroll
        for (int j = 0; j < 4; j++) acc[i][j] = 0.f;

    gemm_bf16_main(g_att, Wm, m0, n0, tid, As, Bs, acc);

    int lane = tid & 31, gid = lane >> 2, tig = lane & 3;
    int warp = tid >> 5, wm = warp & 1, wn = warp >> 1;

    #pragma unroll
    for (int mf = 0; mf < 4; mf++) {
        #pragma unroll
        for (int nf = 0; nf < 4; nf++) {
            float* c = acc[mf*4 + nf];
            int n = n0 + wn*32 + nf*8 + 2*tig;
            float bx = bm[n], by = bm[n+1];
            int m = m0 + wm*64 + mf*16 + gid;
            size_t o = (size_t)m*DD + n;
            float2 r0 = *(const float2*)&y[o];
            *(float2*)&g_x[o] = make_float2(c[0] + bx + r0.x, c[1] + by + r0.y);
            o += (size_t)8*DD;
            float2 r1 = *(const float2*)&y[o];
            *(float2*)&g_x[o] = make_float2(c[2] + bx + r1.x, c[3] + by + r1.y);
        }
    }
}

// ---------------------------------------------------------------------------
// Kernel 2: bf16 mma flash attention (m16n8k16).
// Block = (qt, h, b): 64 q-rows, 4 warps; warp w owns rows w*16..+15.
// K smem [key][hd-pair] pitch 36; V smem [hd][seq-pair] pitch 36 — both give
// fragment bank (4*gid+tig): conflict-free.  S c-layout == PV A-layout after
// pair packing, so NO shuffles in the PV path.
// ---------------------------------------------------------------------------
#define AP 36

__global__ __launch_bounds__(128) void attn_mma(const int* __restrict__ mask)
{
    __shared__ __align__(16) unsigned Kp[64*AP];
    __shared__ __align__(16) unsigned Vp[64*AP];
    __shared__ int Ms[64];

    int qt = blockIdx.x, h = blockIdx.y, b = blockIdx.z;
    int tid = threadIdx.x;
    int lane = tid & 31, w = tid >> 5;
    int gid = lane >> 2, tig = lane & 3;

    // Q fragments (bf16 pairs along hd are memory-adjacent: direct u32 reads)
    unsigned qa[4][4];
    {
        const unsigned* Qw = (const unsigned*)(g_qb +
            ((size_t)(b*HH + h)*SS + qt*64 + w*16 + gid)*HDIM);
        #pragma unroll
        for (int s = 0; s < 4; s++) {
            qa[s][0] = Qw[8*s + tig];
            qa[s][1] = Qw[256 + 8*s + tig];      // row +8 (8*HDIM/2 u32)
            qa[s][2] = Qw[8*s + tig + 4];
            qa[s][3] = Qw[256 + 8*s + tig + 4];
        }
    }

    float oa[8][4];
    #pragma unroll
    for (int i = 0; i < 8; i++)
        #pragma unroll
        for (int j = 0; j < 4; j++) oa[i][j] = 0.f;
    float mrow0 = -3.0e38f, mrow1 = -3.0e38f, lrow0 = 0.f, lrow1 = 0.f;

    const __nv_bfloat16* Kbase = g_kb + (size_t)(b*HH + h)*SS*HDIM;
    const __nv_bfloat16* Vbase = g_vb + (size_t)(b*HH + h)*HDIM*SS;

    for (int t = 0; t < 16; t++) {
        __syncthreads();   // previous tile's mma reads done
        {
            const uint4* Kg = (const uint4*)(Kbase + (size_t)t*64*HDIM);
            #pragma unroll
            for (int it = 0; it < 4; it++) {
                int idx = tid + it*128;          // 0..511 uint4 slots
                int r = idx >> 3, c4 = idx & 7;
                *(uint4*)&Kp[r*AP + c4*4] = Kg[r*8 + c4];           // [key][hd-pairs]
                uint4 vv = *(const uint4*)(Vbase + (size_t)r*SS + t*64 + c4*8);
                *(uint4*)&Vp[r*AP + c4*4] = vv;                     // [hd][seq-pairs]
            }
        }
        if (tid < 16) {
            int4 m4 = *(const int4*)(mask + b*SS + t*64 + tid*4);
            Ms[tid*4 + 0] = m4.x; Ms[tid*4 + 1] = m4.y;
            Ms[tid*4 + 2] = m4.z; Ms[tid*4 + 3] = m4.w;
        }
        __syncthreads();

        // S = Q @ K^T  (16 rows x 64 keys per warp; 4 k16-steps over hd)
        float sf[8][4];
        #pragma unroll
        for (int i = 0; i < 8; i++)
            #pragma unroll
            for (int j = 0; j < 4; j++) sf[i][j] = 0.f;
        #pragma unroll
        for (int s = 0; s < 4; s++) {
            #pragma unroll
            for (int nf = 0; nf < 8; nf++) {
                unsigned bfr[2];
                bfr[0] = Kp[(nf*8 + gid)*AP + 8*s + tig];
                bfr[1] = Kp[(nf*8 + gid)*AP + 8*s + tig + 4];
                mma_bf16(sf[nf], qa[s], bfr);
            }
        }

        // mask (exact -1e9) + 1/sqrt(64) scale
        #pragma unroll
        for (int nf = 0; nf < 8; nf++) {
            int c0 = nf*8 + 2*tig;
            bool km0 = Ms[c0] != 0;
            bool km1 = Ms[c0 + 1] != 0;
            sf[nf][0] = km0 ? -1e9f : sf[nf][0]*0.125f;
            sf[nf][2] = km0 ? -1e9f : sf[nf][2]*0.125f;
            sf[nf][1] = km1 ? -1e9f : sf[nf][1]*0.125f;
            sf[nf][3] = km1 ? -1e9f : sf[nf][3]*0.125f;
        }

        // online softmax: rows r0=gid (slots 0,1), r1=gid+8 (slots 2,3)
        float tm0 = -3.0e38f, tm1 = -3.0e38f;
        #pragma unroll
        for (int nf = 0; nf < 8; nf++) {
            tm0 = fmaxf(tm0, fmaxf(sf[nf][0], sf[nf][1]));
            tm1 = fmaxf(tm1, fmaxf(sf[nf][2], sf[nf][3]));
        }
        tm0 = fmaxf(tm0, __shfl_xor_sync(0xffffffffu, tm0, 1));
        tm0 = fmaxf(tm0, __shfl_xor_sync(0xffffffffu, tm0, 2));
        tm1 = fmaxf(tm1, __shfl_xor_sync(0xffffffffu, tm1, 1));
        tm1 = fmaxf(tm1, __shfl_xor_sync(0xffffffffu, tm1, 2));

        float mn0 = fmaxf(mrow0, tm0), mn1 = fmaxf(mrow1, tm1);
        float al0 = __expf(mrow0 - mn0), al1 = __expf(mrow1 - mn1);
        float ps0 = 0.f, ps1 = 0.f;
        #pragma unroll
        for (int nf = 0; nf < 8; nf++) {
            sf[nf][0] = __expf(sf[nf][0] - mn0);
            sf[nf][1] = __expf(sf[nf][1] - mn0);
            sf[nf][2] = __expf(sf[nf][2] - mn1);
            sf[nf][3] = __expf(sf[nf][3] - mn1);
            ps0 += sf[nf][0] + sf[nf][1];
            ps1 += sf[nf][2] + sf[nf][3];
        }
        ps0 += __shfl_xor_sync(0xffffffffu, ps0, 1);
        ps0 += __shfl_xor_sync(0xffffffffu, ps0, 2);
        ps1 += __shfl_xor_sync(0xffffffffu, ps1, 1);
        ps1 += __shfl_xor_sync(0xffffffffu, ps1, 2);
        lrow0 = lrow0*al0 + ps0;  mrow0 = mn0;
        lrow1 = lrow1*al1 + ps1;  mrow1 = mn1;
        #pragma unroll
        for (int nf = 0; nf < 8; nf++) {
            oa[nf][0] *= al0; oa[nf][1] *= al0;
            oa[nf][2] *= al1; oa[nf][3] *= al1;
        }

        // O += P @ V : S c-layout pairs directly into bf16 A fragments.
        #pragma unroll
        for (int s = 0; s < 4; s++) {
            unsigned pa[4];
            pa[0] = packbf(sf[2*s][0],   sf[2*s][1]);     // P[r0][16s+2tig..+1]
            pa[1] = packbf(sf[2*s][2],   sf[2*s][3]);     // P[r1][...]
            pa[2] = packbf(sf[2*s+1][0], sf[2*s+1][1]);   // P[r0][16s+8+2tig..]
            pa[3] = packbf(sf[2*s+1][2], sf[2*s+1][3]);   // P[r1][...]
            #pragma unroll
            for (int nf = 0; nf < 8; nf++) {
                unsigned bfr[2];
                bfr[0] = Vp[(nf*8 + gid)*AP + 8*s + tig];
                bfr[1] = Vp[(nf*8 + gid)*AP + 8*s + tig + 4];
                mma_bf16(oa[nf], pa, bfr);
            }
        }
    }

    // epilogue: normalize, write [B,S,D] fp32
    float inv0 = 1.f / lrow0, inv1 = 1.f / lrow1;
    int r0 = qt*64 + w*16 + gid;
    #pragma unroll
    for (int nf = 0; nf < 8; nf++) {
        int col = h*HDIM + nf*8 + 2*tig;
        *(float2*)&g_att[((size_t)(b*SS + r0))*DD + col] =
            make_float2(oa[nf][0]*inv0, oa[nf][1]*inv0);
        *(float2*)&g_att[((size_t)(b*SS + r0 + 8))*DD + col] =
            make_float2(oa[nf][2]*inv1, oa[nf][3]*inv1);
    }
}

// ---------------------------------------------------------------------------
// Kernel 4: LayerNorm (torch semantics: unbiased std, eps added to std).
// ---------------------------------------------------------------------------
__global__ __launch_bounds__(256) void ln_kernel(
    const float* __restrict__ a2, const float* __restrict__ b2,
    float* __restrict__ out)
{
    __shared__ float ws[8];
    int row = blockIdx.x;
    int tid = threadIdx.x;
    int lane = tid & 31, wid = tid >> 5;

    const float* x = g_x + (size_t)row * DD;
    float4 v = *(const float4*)(x + tid*4);

    float s = v.x + v.y + v.z + v.w;
    #pragma unroll
    for (int m = 16; m; m >>= 1) s += __shfl_xor_sync(0xffffffffu, s, m);
    if (lane == 0) ws[wid] = s;
    __syncthreads();
    float tot = 0.f;
    #pragma unroll
    for (int i = 0; i < 8; i++) tot += ws[i];
    float mean = tot * (1.f / 1024.f);
    __syncthreads();

    float d0 = v.x - mean, d1 = v.y - mean, d2 = v.z - mean, d3 = v.w - mean;
    float ss = d0*d0 + d1*d1 + d2*d2 + d3*d3;
    #pragma unroll
    for (int m = 16; m; m >>= 1) ss += __shfl_xor_sync(0xffffffffu, ss, m);
    if (lane == 0) ws[wid] = ss;
    __syncthreads();
    float sst = 0.f;
    #pragma unroll
    for (int i = 0; i < 8; i++) sst += ws[i];

    float stdv = sqrtf(sst * (1.f / 1023.f));   // ddof = 1
    float inv = 1.f / (stdv + 1e-6f);           // eps on std

    float4 a = *(const float4*)(a2 + tid*4);
    float4 bb = *(const float4*)(b2 + tid*4);
    float4 o;
    o.x = a.x * d0 * inv + bb.x;
    o.y = a.y * d1 * inv + bb.y;
    o.z = a.z * d2 * inv + bb.z;
    o.w = a.w * d3 * inv + bb.w;
    *(float4*)(out + (size_t)row * DD + tid*4) = o;
}

// ---------------------------------------------------------------------------
// Launch
// ---------------------------------------------------------------------------
extern "C" void kernel_launch(void* const* d_in, const int* in_sizes, int n_in,
                              void* d_out, int out_size)
{
    (void)in_sizes; (void)n_in; (void)out_size;
    const float* y  = (const float*)d_in[0];
    const int* ym   = (const int*)d_in[1];    // jax bool materialized as int32
    const float* Wq = (const float*)d_in[2];
    const float* bq = (const float*)d_in[3];
    const float* Wk = (const float*)d_in[4];
    const float* bk = (const float*)d_in[5];
    const float* Wv = (const float*)d_in[6];
    const float* bv = (const float*)d_in[7];
    const float* Wm = (const float*)d_in[8];
    const float* bm = (const float*)d_in[9];
    const float* a2 = (const float*)d_in[10];
    const float* b2 = (const float*)d_in[11];
    float* out = (float*)d_out;

    qkv_gemm<<<dim3(24, 64), 256>>>(y, Wq, bq, Wk, bk, Wv, bv);
    attn_mma<<<dim3(16, 16, 8), 128>>>(ym);
    proj_gemm<<<dim3(8, 64), 256>>>(Wm, bm, y);
    ln_kernel<<<MR, 256>>>(a2, b2, out);
}